// round 1
// baseline (speedup 1.0000x reference)
#include <cuda_runtime.h>
#include <math.h>

// Problem constants
#define BB 4
#define CC 1024
#define CI_ 512
#define TT 16
#define HH 28
#define WW 28
#define NQ (TT*HH*WW)   // 12544
#define HK 14
#define WK 14
#define NK (TT*HK*WK)   // 3136
#define BN_EPS 1e-5f

// ---------------- scratch (device globals; no allocation allowed) ----------
__device__ float d_xp[(size_t)BB*CC*NK];      // pooled x        51 MB
__device__ float d_theta[(size_t)BB*CI_*NQ];  // theta (B,CI,NQ) 103 MB
__device__ float d_phi[(size_t)BB*CI_*NK];    // phi   (B,CI,NK)  26 MB
__device__ float d_g[(size_t)BB*CI_*NK];      // g     (B,CI,NK)  26 MB
__device__ float d_f[(size_t)BB*NQ*NK];       // attn logits     629 MB
__device__ float d_y[(size_t)BB*CI_*NQ];      // y     (B,CI,NQ) 103 MB
__device__ float d_wy[(size_t)BB*CC*NQ];      // W(y)  (B,C,NQ)  206 MB
__device__ float d_mean[CC];
__device__ float d_invstd[CC];

// ---------------- reductions ----------------
__device__ __forceinline__ float warpMax(float v) {
    #pragma unroll
    for (int o = 16; o > 0; o >>= 1) v = fmaxf(v, __shfl_xor_sync(0xffffffffu, v, o));
    return v;
}
__device__ __forceinline__ float warpSum(float v) {
    #pragma unroll
    for (int o = 16; o > 0; o >>= 1) v += __shfl_xor_sync(0xffffffffu, v, o);
    return v;
}

// ---------------- generic batched SGEMM ----------------
// C[m,n] = scale * sum_k opA(A)[m,k] * opB(B)[k,n]  (+ bias[m])
// OPA==0: A is MxK row-major (lda=K-ish).  OPA==1: A is KxM row-major (lda=M-ish), i.e. A^T.
// OPB==0: B is KxN row-major.              OPB==1: B is NxK row-major, i.e. B^T.
template<int OPA, int OPB>
__global__ __launch_bounds__(256)
void sgemm_kernel(const float* __restrict__ A, const float* __restrict__ B,
                  float* __restrict__ C,
                  int M, int N, int K,
                  int lda, int ldb, int ldc,
                  long long strideA, long long strideB, long long strideC,
                  const float* __restrict__ bias, float scale)
{
    __shared__ float As[8][128];
    __shared__ float Bs[8][128];

    const int bz = blockIdx.z;
    A += (long long)bz * strideA;
    B += (long long)bz * strideB;
    C += (long long)bz * strideC;

    const int row0 = blockIdx.y * 128;   // m
    const int col0 = blockIdx.x * 128;   // n
    const int tid = threadIdx.x;         // 0..255
    const int tx = tid & 15;             // n sub-tile
    const int ty = tid >> 4;             // m sub-tile

    float acc[8][8];
    #pragma unroll
    for (int i = 0; i < 8; i++)
        #pragma unroll
        for (int j = 0; j < 8; j++) acc[i][j] = 0.0f;

    for (int k0 = 0; k0 < K; k0 += 8) {
        // load A tile 128(m) x 8(k)
        #pragma unroll
        for (int l = 0; l < 4; l++) {
            int idx = tid + l * 256;
            int m, kk;
            if (OPA == 0) { kk = idx & 7;  m = idx >> 3; }
            else          { m = idx & 127; kk = idx >> 7; }
            int gm = row0 + m, gk = k0 + kk;
            float v = 0.0f;
            if (gm < M && gk < K)
                v = (OPA == 0) ? A[(long long)gm * lda + gk]
                               : A[(long long)gk * lda + gm];
            As[kk][m] = v;
        }
        // load B tile 8(k) x 128(n)
        #pragma unroll
        for (int l = 0; l < 4; l++) {
            int idx = tid + l * 256;
            int n, kk;
            if (OPB == 0) { n = idx & 127; kk = idx >> 7; }
            else          { kk = idx & 7;  n = idx >> 3; }
            int gn = col0 + n, gk = k0 + kk;
            float v = 0.0f;
            if (gn < N && gk < K)
                v = (OPB == 0) ? B[(long long)gk * ldb + gn]
                               : B[(long long)gn * ldb + gk];
            Bs[kk][n] = v;
        }
        __syncthreads();

        #pragma unroll
        for (int kk = 0; kk < 8; kk++) {
            float ra[8], rb[8];
            #pragma unroll
            for (int i = 0; i < 8; i++) ra[i] = As[kk][ty * 8 + i];
            #pragma unroll
            for (int j = 0; j < 8; j++) rb[j] = Bs[kk][tx * 8 + j];
            #pragma unroll
            for (int i = 0; i < 8; i++)
                #pragma unroll
                for (int j = 0; j < 8; j++)
                    acc[i][j] = fmaf(ra[i], rb[j], acc[i][j]);
        }
        __syncthreads();
    }

    #pragma unroll
    for (int i = 0; i < 8; i++) {
        int gm = row0 + ty * 8 + i;
        if (gm >= M) continue;
        float bv = bias ? bias[gm] : 0.0f;
        #pragma unroll
        for (int j = 0; j < 8; j++) {
            int gn = col0 + tx * 8 + j;
            if (gn < N)
                C[(long long)gm * ldc + gn] = acc[i][j] * scale + bv;
        }
    }
}

// ---------------- maxpool (1,2,2) on spatial dims ----------------
__global__ void maxpool_kernel(const float* __restrict__ x)
{
    long long i = (long long)blockIdx.x * 256 + threadIdx.x;
    if (i >= (long long)BB * CC * NK) return;
    int j = (int)(i % WK);
    long long r = i / WK;
    int ii = (int)(r % HK); r /= HK;
    int t  = (int)(r % TT); r /= TT;          // r = b*CC + c
    long long base = ((r * TT + t) * HH + 2 * ii) * WW + 2 * j;
    float v = fmaxf(fmaxf(x[base], x[base + 1]),
                    fmaxf(x[base + WW], x[base + WW + 1]));
    d_xp[i] = v;
}

// ---------------- softmax over rows of length NK (in place) ----------------
__global__ void softmax_kernel()
{
    long long row = blockIdx.x;
    float* p = d_f + row * (long long)NK;
    int tid = threadIdx.x;
    __shared__ float red[8];

    float m = -1e30f;
    for (int i = tid; i < NK; i += 256) m = fmaxf(m, p[i]);
    m = warpMax(m);
    if ((tid & 31) == 0) red[tid >> 5] = m;
    __syncthreads();
    if (tid < 32) {
        float v = (tid < 8) ? red[tid] : -1e30f;
        v = warpMax(v);
        if (tid == 0) red[0] = v;
    }
    __syncthreads();
    const float bm = red[0];
    __syncthreads();

    float s = 0.0f;
    for (int i = tid; i < NK; i += 256) {
        float e = __expf(p[i] - bm);
        p[i] = e;
        s += e;
    }
    s = warpSum(s);
    if ((tid & 31) == 0) red[tid >> 5] = s;
    __syncthreads();
    if (tid < 32) {
        float v = (tid < 8) ? red[tid] : 0.0f;
        v = warpSum(v);
        if (tid == 0) red[0] = v;
    }
    __syncthreads();
    const float inv = 1.0f / red[0];
    for (int i = tid; i < NK; i += 256) p[i] *= inv;
}

// ---------------- BN statistics over (b, n) per channel ----------------
__global__ void bn_stats_kernel()
{
    int c = blockIdx.x;
    int tid = threadIdx.x;
    float s = 0.0f, ss = 0.0f;
    for (int b = 0; b < BB; b++) {
        const float* p = d_wy + ((long long)b * CC + c) * NQ;
        for (int i = tid; i < NQ; i += 256) {
            float v = p[i];
            s += v; ss += v * v;
        }
    }
    __shared__ float r1[8], r2[8];
    s = warpSum(s); ss = warpSum(ss);
    if ((tid & 31) == 0) { r1[tid >> 5] = s; r2[tid >> 5] = ss; }
    __syncthreads();
    if (tid < 32) {
        float a  = (tid < 8) ? r1[tid] : 0.0f;
        float b2 = (tid < 8) ? r2[tid] : 0.0f;
        a = warpSum(a); b2 = warpSum(b2);
        if (tid == 0) {
            const float cnt = (float)((long long)BB * NQ);
            float mean = a / cnt;
            float var = b2 / cnt - mean * mean;
            d_mean[c] = mean;
            d_invstd[c] = rsqrtf(var + BN_EPS);
        }
    }
}

// ---------------- BN apply + residual ----------------
__global__ void bn_apply_kernel(const float* __restrict__ x,
                                const float* __restrict__ gamma,
                                const float* __restrict__ beta,
                                float* __restrict__ out)
{
    long long i = (long long)blockIdx.x * 256 + threadIdx.x;
    if (i >= (long long)BB * CC * NQ) return;
    int c = (int)((i / NQ) % CC);
    out[i] = (d_wy[i] - d_mean[c]) * d_invstd[c] * gamma[c] + beta[c] + x[i];
}

// ---------------- host launch ----------------
extern "C" void kernel_launch(void* const* d_in, const int* in_sizes, int n_in,
                              void* d_out, int out_size)
{
    (void)in_sizes; (void)n_in; (void)out_size;
    const float* x       = (const float*)d_in[0];
    const float* theta_w = (const float*)d_in[1];
    const float* theta_b = (const float*)d_in[2];
    const float* phi_w   = (const float*)d_in[3];
    const float* phi_b   = (const float*)d_in[4];
    const float* g_w     = (const float*)d_in[5];
    const float* g_b     = (const float*)d_in[6];
    const float* w_w     = (const float*)d_in[7];
    const float* w_b     = (const float*)d_in[8];
    const float* bn_g    = (const float*)d_in[9];
    const float* bn_b    = (const float*)d_in[10];
    float* out = (float*)d_out;

    void *p_xp, *p_theta, *p_phi, *p_g, *p_f, *p_y, *p_wy;
    cudaGetSymbolAddress(&p_xp, d_xp);
    cudaGetSymbolAddress(&p_theta, d_theta);
    cudaGetSymbolAddress(&p_phi, d_phi);
    cudaGetSymbolAddress(&p_g, d_g);
    cudaGetSymbolAddress(&p_f, d_f);
    cudaGetSymbolAddress(&p_y, d_y);
    cudaGetSymbolAddress(&p_wy, d_wy);

    const float fscale = 1.0f / sqrtf((float)CI_);

    // 1) maxpool
    {
        long long tot = (long long)BB * CC * NK;
        maxpool_kernel<<<(unsigned)((tot + 255) / 256), 256>>>(x);
    }

    // 2) theta = theta_w @ x + theta_b          (B, CI, NQ)
    sgemm_kernel<0,0><<<dim3((NQ + 127) / 128, (CI_ + 127) / 128, BB), 256>>>(
        theta_w, x, (float*)p_theta,
        CI_, NQ, CC, CC, NQ, NQ,
        0LL, (long long)CC * NQ, (long long)CI_ * NQ, theta_b, 1.0f);

    // 3) phi = phi_w @ xp + phi_b               (B, CI, NK)
    sgemm_kernel<0,0><<<dim3((NK + 127) / 128, (CI_ + 127) / 128, BB), 256>>>(
        phi_w, (const float*)p_xp, (float*)p_phi,
        CI_, NK, CC, CC, NK, NK,
        0LL, (long long)CC * NK, (long long)CI_ * NK, phi_b, 1.0f);

    // 4) g = g_w @ xp + g_b                     (B, CI, NK)
    sgemm_kernel<0,0><<<dim3((NK + 127) / 128, (CI_ + 127) / 128, BB), 256>>>(
        g_w, (const float*)p_xp, (float*)p_g,
        CI_, NK, CC, CC, NK, NK,
        0LL, (long long)CC * NK, (long long)CI_ * NK, g_b, 1.0f);

    // 5) f = theta^T @ phi * ci^-0.5            (B, NQ, NK)
    sgemm_kernel<1,0><<<dim3((NK + 127) / 128, (NQ + 127) / 128, BB), 256>>>(
        (const float*)p_theta, (const float*)p_phi, (float*)p_f,
        NQ, NK, CI_, NQ, NK, NK,
        (long long)CI_ * NQ, (long long)CI_ * NK, (long long)NQ * NK, nullptr, fscale);

    // 6) softmax rows (in place)
    softmax_kernel<<<BB * NQ, 256>>>();

    // 7) y = g @ attn^T                          (B, CI, NQ)
    sgemm_kernel<0,1><<<dim3((NQ + 127) / 128, (CI_ + 127) / 128, BB), 256>>>(
        (const float*)p_g, (const float*)p_f, (float*)p_y,
        CI_, NQ, NK, NK, NK, NQ,
        (long long)CI_ * NK, (long long)NQ * NK, (long long)CI_ * NQ, nullptr, 1.0f);

    // 8) wy = w_w @ y + w_b                      (B, C, NQ)
    sgemm_kernel<0,0><<<dim3((NQ + 127) / 128, (CC + 127) / 128, BB), 256>>>(
        w_w, (const float*)p_y, (float*)p_wy,
        CC, NQ, CI_, CI_, NQ, NQ,
        0LL, (long long)CI_ * NQ, (long long)CC * NQ, w_b, 1.0f);

    // 9) BN stats
    bn_stats_kernel<<<CC, 256>>>();

    // 10) BN apply + residual
    {
        long long tot = (long long)BB * CC * NQ;
        bn_apply_kernel<<<(unsigned)((tot + 255) / 256), 256>>>(x, bn_g, bn_b, out);
    }
}

// round 2
// speedup vs baseline: 1.0142x; 1.0142x over previous
#include <cuda_runtime.h>
#include <math.h>

// Problem constants
#define BB 4
#define CC 1024
#define CI_ 512
#define TT 16
#define HH 28
#define WW 28
#define NQ (TT*HH*WW)   // 12544
#define HK 14
#define WK 14
#define NK (TT*HK*WK)   // 3136
#define BN_EPS 1e-5f

// ---------------- scratch (device globals; no allocation allowed) ----------
__device__ float d_xp[(size_t)BB*CC*NK];      // pooled x        51 MB
__device__ float d_theta[(size_t)BB*CI_*NQ];  // theta (B,CI,NQ) 103 MB
__device__ float d_phi[(size_t)BB*CI_*NK];    // phi   (B,CI,NK)  26 MB
__device__ float d_g[(size_t)BB*CI_*NK];      // g     (B,CI,NK)  26 MB
__device__ float d_f[(size_t)BB*NQ*NK];       // attn logits     629 MB
__device__ float d_y[(size_t)BB*CI_*NQ];      // y     (B,CI,NQ) 103 MB
__device__ float d_wy[(size_t)BB*CC*NQ];      // W(y)  (B,C,NQ)  206 MB
__device__ float d_mean[CC];
__device__ float d_invstd[CC];

// ---------------- reductions ----------------
__device__ __forceinline__ float warpMax(float v) {
    #pragma unroll
    for (int o = 16; o > 0; o >>= 1) v = fmaxf(v, __shfl_xor_sync(0xffffffffu, v, o));
    return v;
}
__device__ __forceinline__ float warpSum(float v) {
    #pragma unroll
    for (int o = 16; o > 0; o >>= 1) v += __shfl_xor_sync(0xffffffffu, v, o);
    return v;
}

// ---------------- generic batched SGEMM ----------------
// C[m,n] = scale * sum_k opA(A)[m,k] * opB(B)[k,n]  (+ bias[m])
// OPA==0: A is MxK row-major (lda=K-ish).  OPA==1: A is KxM row-major (lda=M-ish), i.e. A^T.
// OPB==0: B is KxN row-major.              OPB==1: B is NxK row-major, i.e. B^T.
template<int OPA, int OPB>
__global__ __launch_bounds__(256)
void sgemm_kernel(const float* __restrict__ A, const float* __restrict__ B,
                  float* __restrict__ C,
                  int M, int N, int K,
                  int lda, int ldb, int ldc,
                  long long strideA, long long strideB, long long strideC,
                  const float* __restrict__ bias, float scale)
{
    __shared__ float As[8][128];
    __shared__ float Bs[8][128];

    const int bz = blockIdx.z;
    A += (long long)bz * strideA;
    B += (long long)bz * strideB;
    C += (long long)bz * strideC;

    const int row0 = blockIdx.y * 128;   // m
    const int col0 = blockIdx.x * 128;   // n
    const int tid = threadIdx.x;         // 0..255
    const int tx = tid & 15;             // n sub-tile
    const int ty = tid >> 4;             // m sub-tile

    float acc[8][8];
    #pragma unroll
    for (int i = 0; i < 8; i++)
        #pragma unroll
        for (int j = 0; j < 8; j++) acc[i][j] = 0.0f;

    for (int k0 = 0; k0 < K; k0 += 8) {
        // load A tile 128(m) x 8(k)
        #pragma unroll
        for (int l = 0; l < 4; l++) {
            int idx = tid + l * 256;
            int m, kk;
            if (OPA == 0) { kk = idx & 7;  m = idx >> 3; }
            else          { m = idx & 127; kk = idx >> 7; }
            int gm = row0 + m, gk = k0 + kk;
            float v = 0.0f;
            if (gm < M && gk < K)
                v = (OPA == 0) ? A[(long long)gm * lda + gk]
                               : A[(long long)gk * lda + gm];
            As[kk][m] = v;
        }
        // load B tile 8(k) x 128(n)
        #pragma unroll
        for (int l = 0; l < 4; l++) {
            int idx = tid + l * 256;
            int n, kk;
            if (OPB == 0) { n = idx & 127; kk = idx >> 7; }
            else          { kk = idx & 7;  n = idx >> 3; }
            int gn = col0 + n, gk = k0 + kk;
            float v = 0.0f;
            if (gn < N && gk < K)
                v = (OPB == 0) ? B[(long long)gk * ldb + gn]
                               : B[(long long)gn * ldb + gk];
            Bs[kk][n] = v;
        }
        __syncthreads();

        #pragma unroll
        for (int kk = 0; kk < 8; kk++) {
            float ra[8], rb[8];
            #pragma unroll
            for (int i = 0; i < 8; i++) ra[i] = As[kk][ty * 8 + i];
            #pragma unroll
            for (int j = 0; j < 8; j++) rb[j] = Bs[kk][tx * 8 + j];
            #pragma unroll
            for (int i = 0; i < 8; i++)
                #pragma unroll
                for (int j = 0; j < 8; j++)
                    acc[i][j] = fmaf(ra[i], rb[j], acc[i][j]);
        }
        __syncthreads();
    }

    #pragma unroll
    for (int i = 0; i < 8; i++) {
        int gm = row0 + ty * 8 + i;
        if (gm >= M) continue;
        float bv = bias ? bias[gm] : 0.0f;
        #pragma unroll
        for (int j = 0; j < 8; j++) {
            int gn = col0 + tx * 8 + j;
            if (gn < N)
                C[(long long)gm * ldc + gn] = acc[i][j] * scale + bv;
        }
    }
}

// ---------------- maxpool (1,2,2) on spatial dims ----------------
__global__ void maxpool_kernel(const float* __restrict__ x)
{
    long long i = (long long)blockIdx.x * 256 + threadIdx.x;
    if (i >= (long long)BB * CC * NK) return;
    int j = (int)(i % WK);
    long long r = i / WK;
    int ii = (int)(r % HK); r /= HK;
    int t  = (int)(r % TT); r /= TT;          // r = b*CC + c
    long long base = ((r * TT + t) * HH + 2 * ii) * WW + 2 * j;
    float v = fmaxf(fmaxf(x[base], x[base + 1]),
                    fmaxf(x[base + WW], x[base + WW + 1]));
    d_xp[i] = v;
}

// ---------------- softmax over rows of length NK (in place) ----------------
__global__ void softmax_kernel()
{
    long long row = blockIdx.x;
    float* p = d_f + row * (long long)NK;
    int tid = threadIdx.x;
    __shared__ float red[8];

    float m = -1e30f;
    for (int i = tid; i < NK; i += 256) m = fmaxf(m, p[i]);
    m = warpMax(m);
    if ((tid & 31) == 0) red[tid >> 5] = m;
    __syncthreads();
    if (tid < 32) {
        float v = (tid < 8) ? red[tid] : -1e30f;
        v = warpMax(v);
        if (tid == 0) red[0] = v;
    }
    __syncthreads();
    const float bm = red[0];
    __syncthreads();

    float s = 0.0f;
    for (int i = tid; i < NK; i += 256) {
        float e = __expf(p[i] - bm);
        p[i] = e;
        s += e;
    }
    s = warpSum(s);
    if ((tid & 31) == 0) red[tid >> 5] = s;
    __syncthreads();
    if (tid < 32) {
        float v = (tid < 8) ? red[tid] : 0.0f;
        v = warpSum(v);
        if (tid == 0) red[0] = v;
    }
    __syncthreads();
    const float inv = 1.0f / red[0];
    for (int i = tid; i < NK; i += 256) p[i] *= inv;
}

// ---------------- BN statistics over (b, n) per channel ----------------
__global__ void bn_stats_kernel()
{
    int c = blockIdx.x;
    int tid = threadIdx.x;
    float s = 0.0f, ss = 0.0f;
    for (int b = 0; b < BB; b++) {
        const float* p = d_wy + ((long long)b * CC + c) * NQ;
        for (int i = tid; i < NQ; i += 256) {
            float v = p[i];
            s += v; ss += v * v;
        }
    }
    __shared__ float r1[8], r2[8];
    s = warpSum(s); ss = warpSum(ss);
    if ((tid & 31) == 0) { r1[tid >> 5] = s; r2[tid >> 5] = ss; }
    __syncthreads();
    if (tid < 32) {
        float a  = (tid < 8) ? r1[tid] : 0.0f;
        float b2 = (tid < 8) ? r2[tid] : 0.0f;
        a = warpSum(a); b2 = warpSum(b2);
        if (tid == 0) {
            const float cnt = (float)((long long)BB * NQ);
            float mean = a / cnt;
            float var = b2 / cnt - mean * mean;
            d_mean[c] = mean;
            d_invstd[c] = rsqrtf(var + BN_EPS);
        }
    }
}

// ---------------- BN apply + residual ----------------
__global__ void bn_apply_kernel(const float* __restrict__ x,
                                const float* __restrict__ gamma,
                                const float* __restrict__ beta,
                                float* __restrict__ out)
{
    long long i = (long long)blockIdx.x * 256 + threadIdx.x;
    if (i >= (long long)BB * CC * NQ) return;
    int c = (int)((i / NQ) % CC);
    out[i] = (d_wy[i] - d_mean[c]) * d_invstd[c] * gamma[c] + beta[c] + x[i];
}

// ---------------- host launch ----------------
extern "C" void kernel_launch(void* const* d_in, const int* in_sizes, int n_in,
                              void* d_out, int out_size)
{
    (void)in_sizes; (void)n_in; (void)out_size;
    const float* x       = (const float*)d_in[0];
    const float* theta_w = (const float*)d_in[1];
    const float* theta_b = (const float*)d_in[2];
    const float* phi_w   = (const float*)d_in[3];
    const float* phi_b   = (const float*)d_in[4];
    const float* g_w     = (const float*)d_in[5];
    const float* g_b     = (const float*)d_in[6];
    const float* w_w     = (const float*)d_in[7];
    const float* w_b     = (const float*)d_in[8];
    const float* bn_g    = (const float*)d_in[9];
    const float* bn_b    = (const float*)d_in[10];
    float* out = (float*)d_out;

    void *p_xp, *p_theta, *p_phi, *p_g, *p_f, *p_y, *p_wy;
    cudaGetSymbolAddress(&p_xp, d_xp);
    cudaGetSymbolAddress(&p_theta, d_theta);
    cudaGetSymbolAddress(&p_phi, d_phi);
    cudaGetSymbolAddress(&p_g, d_g);
    cudaGetSymbolAddress(&p_f, d_f);
    cudaGetSymbolAddress(&p_y, d_y);
    cudaGetSymbolAddress(&p_wy, d_wy);

    const float fscale = 1.0f / sqrtf((float)CI_);

    // 1) maxpool
    {
        long long tot = (long long)BB * CC * NK;
        maxpool_kernel<<<(unsigned)((tot + 255) / 256), 256>>>(x);
    }

    // 2) theta = theta_w @ x + theta_b          (B, CI, NQ)
    sgemm_kernel<0,0><<<dim3((NQ + 127) / 128, (CI_ + 127) / 128, BB), 256>>>(
        theta_w, x, (float*)p_theta,
        CI_, NQ, CC, CC, NQ, NQ,
        0LL, (long long)CC * NQ, (long long)CI_ * NQ, theta_b, 1.0f);

    // 3) phi = phi_w @ xp + phi_b               (B, CI, NK)
    sgemm_kernel<0,0><<<dim3((NK + 127) / 128, (CI_ + 127) / 128, BB), 256>>>(
        phi_w, (const float*)p_xp, (float*)p_phi,
        CI_, NK, CC, CC, NK, NK,
        0LL, (long long)CC * NK, (long long)CI_ * NK, phi_b, 1.0f);

    // 4) g = g_w @ xp + g_b                     (B, CI, NK)
    sgemm_kernel<0,0><<<dim3((NK + 127) / 128, (CI_ + 127) / 128, BB), 256>>>(
        g_w, (const float*)p_xp, (float*)p_g,
        CI_, NK, CC, CC, NK, NK,
        0LL, (long long)CC * NK, (long long)CI_ * NK, g_b, 1.0f);

    // 5) f = theta^T @ phi * ci^-0.5            (B, NQ, NK)
    sgemm_kernel<1,0><<<dim3((NK + 127) / 128, (NQ + 127) / 128, BB), 256>>>(
        (const float*)p_theta, (const float*)p_phi, (float*)p_f,
        NQ, NK, CI_, NQ, NK, NK,
        (long long)CI_ * NQ, (long long)CI_ * NK, (long long)NQ * NK, nullptr, fscale);

    // 6) softmax rows (in place)
    softmax_kernel<<<BB * NQ, 256>>>();

    // 7) y = g @ attn^T                          (B, CI, NQ)
    sgemm_kernel<0,1><<<dim3((NQ + 127) / 128, (CI_ + 127) / 128, BB), 256>>>(
        (const float*)p_g, (const float*)p_f, (float*)p_y,
        CI_, NQ, NK, NK, NK, NQ,
        (long long)CI_ * NK, (long long)NQ * NK, (long long)CI_ * NQ, nullptr, 1.0f);

    // 8) wy = w_w @ y + w_b                      (B, C, NQ)
    sgemm_kernel<0,0><<<dim3((NQ + 127) / 128, (CC + 127) / 128, BB), 256>>>(
        w_w, (const float*)p_y, (float*)p_wy,
        CC, NQ, CI_, CI_, NQ, NQ,
        0LL, (long long)CI_ * NQ, (long long)CC * NQ, w_b, 1.0f);

    // 9) BN stats
    bn_stats_kernel<<<CC, 256>>>();

    // 10) BN apply + residual
    {
        long long tot = (long long)BB * CC * NQ;
        bn_apply_kernel<<<(unsigned)((tot + 255) / 256), 256>>>(x, bn_g, bn_b, out);
    }
}

// round 4
// speedup vs baseline: 3.4456x; 3.3974x over previous
#include <cuda_runtime.h>
#include <math.h>
#include <stdint.h>

#define BB 4
#define CC 1024
#define CI 512
#define TT 16
#define HH 28
#define WW 28
#define NQ 12544
#define NKr 3136
#define NKp 3200
#define BN_EPS 1e-5f

// ---------------- scratch ----------------
__device__ __align__(256) float d_xt [(size_t)BB*NQ*CC];
__device__ __align__(256) float d_xpt[(size_t)BB*NKp*CC];
__device__ __align__(256) float d_th [(size_t)BB*NQ*CI];
__device__ __align__(256) float d_ph [(size_t)BB*NKp*CI];
__device__ __align__(256) float d_g2 [(size_t)BB*CI*NKp];
__device__ __align__(256) float d_f  [(size_t)BB*NQ*NKp];
__device__ __align__(256) float d_y  [(size_t)BB*NQ*CI];
__device__ __align__(256) float d_wy [(size_t)BB*CC*NQ];
__device__ float d_mean[CC];
__device__ float d_istd[CC];

// ---------------- helpers ----------------
__device__ __forceinline__ uint32_t s2u(const void* p) {
    uint32_t a;
    asm("{ .reg .u64 t; cvta.to.shared.u64 t, %1; cvt.u32.u64 %0, t; }" : "=r"(a) : "l"(p));
    return a;
}
__device__ __forceinline__ float warpMax(float v) {
    #pragma unroll
    for (int o = 16; o > 0; o >>= 1) v = fmaxf(v, __shfl_xor_sync(0xffffffffu, v, o));
    return v;
}
__device__ __forceinline__ float warpSum(float v) {
    #pragma unroll
    for (int o = 16; o > 0; o >>= 1) v += __shfl_xor_sync(0xffffffffu, v, o);
    return v;
}

// ---------------- tf32 mma.sync TN GEMM ----------------
// D[M,N] = scale * A[M,K] @ B[N,K]^T (+ biasM[m]) (+ biasN[n])
// M,N multiples of 128 (grid), K multiple of 32. grid=(N/128, M/128, batch)
#define LDS_P 36                       // padded row length (floats)
#define STG   (2*128*LDS_P)            // floats per stage (A tile + B tile)
#define NSTAGE 4
#define GEMM_SMEM (NSTAGE*STG*4)       // 147456 bytes

__global__ __launch_bounds__(256, 1)
void gemm_tn(const float* __restrict__ A, const float* __restrict__ B,
             float* __restrict__ D, int K, int lda, int ldb, int ldd,
             long long sA, long long sB, long long sD,
             const float* __restrict__ biasM, const float* __restrict__ biasN,
             float scale)
{
    extern __shared__ float smem[];
    const int tid = threadIdx.x, wid = tid >> 5, lane = tid & 31;
    const int wm = wid >> 2, wn = wid & 3;        // warp tile: 64 x 32
    const int g = lane >> 2, tg = lane & 3;
    const int m0 = blockIdx.y << 7, n0 = blockIdx.x << 7;
    A += (long long)blockIdx.z * sA + (size_t)m0 * lda;
    B += (long long)blockIdx.z * sB + (size_t)n0 * ldb;
    D += (long long)blockIdx.z * sD;
    const int ktiles = K >> 5;

    // producer mapping: 1024 chunks of 16B per tile; thread handles 4 chunks
    const int prow[4] = { (tid + 0) >> 3, (tid + 256) >> 3, (tid + 512) >> 3, (tid + 768) >> 3 };
    const int pc = tid & 7;

    float acc[4][4][4];
    #pragma unroll
    for (int i = 0; i < 4; i++)
        #pragma unroll
        for (int j = 0; j < 4; j++)
            #pragma unroll
            for (int q = 0; q < 4; q++) acc[i][j][q] = 0.0f;

    // prologue: fill stages 0..NSTAGE-2
    #pragma unroll
    for (int s = 0; s < NSTAGE - 1; s++) {
        const float* Ab = A + (s << 5) + (pc << 2);
        const float* Bb = B + (s << 5) + (pc << 2);
        uint32_t Sa = s2u(smem + s * STG) + pc * 16;
        uint32_t Sb = Sa + 128 * LDS_P * 4;
        #pragma unroll
        for (int l = 0; l < 4; l++) {
            asm volatile("cp.async.cg.shared.global [%0], [%1], 16;"
                         :: "r"(Sa + prow[l] * (LDS_P*4)), "l"(Ab + (size_t)prow[l] * lda));
            asm volatile("cp.async.cg.shared.global [%0], [%1], 16;"
                         :: "r"(Sb + prow[l] * (LDS_P*4)), "l"(Bb + (size_t)prow[l] * ldb));
        }
        asm volatile("cp.async.commit_group;");
    }

    for (int kt = 0; kt < ktiles; kt++) {
        // prefetch stage kt+NSTAGE-1
        const int pf = kt + NSTAGE - 1;
        if (pf < ktiles) {
            const int s = pf & (NSTAGE - 1);
            const float* Ab = A + (pf << 5) + (pc << 2);
            const float* Bb = B + (pf << 5) + (pc << 2);
            uint32_t Sa = s2u(smem + s * STG) + pc * 16;
            uint32_t Sb = Sa + 128 * LDS_P * 4;
            #pragma unroll
            for (int l = 0; l < 4; l++) {
                asm volatile("cp.async.cg.shared.global [%0], [%1], 16;"
                             :: "r"(Sa + prow[l] * (LDS_P*4)), "l"(Ab + (size_t)prow[l] * lda));
                asm volatile("cp.async.cg.shared.global [%0], [%1], 16;"
                             :: "r"(Sb + prow[l] * (LDS_P*4)), "l"(Bb + (size_t)prow[l] * ldb));
            }
        }
        asm volatile("cp.async.commit_group;");
        asm volatile("cp.async.wait_group %0;" :: "n"(NSTAGE - 2));
        __syncthreads();

        const float* Sa = smem + (kt & (NSTAGE - 1)) * STG + (wm * 64 + g) * LDS_P;
        const float* Sb = smem + (kt & (NSTAGE - 1)) * STG + 128 * LDS_P + (wn * 32 + g) * LDS_P;

        #pragma unroll
        for (int ks = 0; ks < 4; ks++) {
            const int kc = (ks << 3) + tg;
            uint32_t a[4][4], b[4][2];
            #pragma unroll
            for (int mt = 0; mt < 4; mt++) {
                const float* p = Sa + mt * 16 * LDS_P + kc;
                a[mt][0] = __float_as_uint(p[0]);
                a[mt][1] = __float_as_uint(p[8 * LDS_P]);
                a[mt][2] = __float_as_uint(p[4]);
                a[mt][3] = __float_as_uint(p[8 * LDS_P + 4]);
            }
            #pragma unroll
            for (int nt = 0; nt < 4; nt++) {
                const float* p = Sb + nt * 8 * LDS_P + kc;
                b[nt][0] = __float_as_uint(p[0]);
                b[nt][1] = __float_as_uint(p[4]);
            }
            #pragma unroll
            for (int mt = 0; mt < 4; mt++)
                #pragma unroll
                for (int nt = 0; nt < 4; nt++)
                    asm("mma.sync.aligned.m16n8k8.row.col.f32.tf32.tf32.f32 "
                        "{%0,%1,%2,%3}, {%4,%5,%6,%7}, {%8,%9}, {%0,%1,%2,%3};"
                        : "+f"(acc[mt][nt][0]), "+f"(acc[mt][nt][1]),
                          "+f"(acc[mt][nt][2]), "+f"(acc[mt][nt][3])
                        : "r"(a[mt][0]), "r"(a[mt][1]), "r"(a[mt][2]), "r"(a[mt][3]),
                          "r"(b[nt][0]), "r"(b[nt][1]));
        }
        __syncthreads();
    }

    // epilogue
    #pragma unroll
    for (int mt = 0; mt < 4; mt++) {
        const int r0 = m0 + wm * 64 + mt * 16 + g;
        const float bm0 = biasM ? biasM[r0] : 0.0f;
        const float bm1 = biasM ? biasM[r0 + 8] : 0.0f;
        #pragma unroll
        for (int nt = 0; nt < 4; nt++) {
            const int col = n0 + wn * 32 + nt * 8 + tg * 2;
            const float bn0 = biasN ? biasN[col] : 0.0f;
            const float bn1 = biasN ? biasN[col + 1] : 0.0f;
            float2 v0, v1;
            v0.x = acc[mt][nt][0] * scale + bm0 + bn0;
            v0.y = acc[mt][nt][1] * scale + bm0 + bn1;
            v1.x = acc[mt][nt][2] * scale + bm1 + bn0;
            v1.y = acc[mt][nt][3] * scale + bm1 + bn1;
            *(float2*)(D + (size_t)r0 * ldd + col) = v0;
            *(float2*)(D + (size_t)(r0 + 8) * ldd + col) = v1;
        }
    }
}

// ---------------- transpose x (B,C,NQ) -> xt (B,NQ,C) ----------------
__global__ void transpose_x(const float* __restrict__ x)
{
    __shared__ float t[32][33];
    const int b = blockIdx.z;
    const int n0 = blockIdx.x << 5, c0 = blockIdx.y << 5;
    const int tx = threadIdx.x, ty = threadIdx.y;
    const float* xp = x + (size_t)b * CC * NQ;
    float* xo = d_xt + (size_t)b * NQ * CC;
    #pragma unroll
    for (int i = 0; i < 4; i++)
        t[ty + i*8][tx] = xp[(size_t)(c0 + ty + i*8) * NQ + n0 + tx];
    __syncthreads();
    #pragma unroll
    for (int i = 0; i < 4; i++)
        xo[(size_t)(n0 + ty + i*8) * CC + c0 + tx] = t[tx][ty + i*8];
}

// ---------------- pool xt -> xpt (B,NKp,C), pad rows zero ----------------
__global__ void pool_kernel()
{
    const int b = blockIdx.y, nk = blockIdx.x;
    float* o = d_xpt + ((size_t)b * NKp + nk) * CC;
    if (nk >= NKr) {
        for (int c = threadIdx.x; c < CC; c += 256) o[c] = 0.0f;
        return;
    }
    const int wi = nk % 14, hi = (nk / 14) % 14, t = nk / 196;
    const float* r0 = d_xt + ((size_t)b * NQ + (size_t)(t * HH + 2 * hi) * WW + 2 * wi) * CC;
    for (int c = threadIdx.x; c < CC; c += 256)
        o[c] = fmaxf(fmaxf(r0[c], r0[CC + c]), fmaxf(r0[(size_t)WW*CC + c], r0[(size_t)(WW+1)*CC + c]));
}

// ---------------- softmax rows of d_f (len NKp, valid NKr), zero pads ------
__global__ void softmax_kernel()
{
    float* p = d_f + (size_t)blockIdx.x * NKp;
    const int tid = threadIdx.x;
    __shared__ float red[8];
    float m = -1e30f;
    for (int i = tid; i < NKr; i += 256) m = fmaxf(m, p[i]);
    m = warpMax(m);
    if ((tid & 31) == 0) red[tid >> 5] = m;
    __syncthreads();
    if (tid < 32) { float v = (tid < 8) ? red[tid] : -1e30f; v = warpMax(v); if (tid == 0) red[0] = v; }
    __syncthreads();
    const float bm = red[0];
    __syncthreads();
    float s = 0.0f;
    for (int i = tid; i < NKr; i += 256) { float e = __expf(p[i] - bm); p[i] = e; s += e; }
    s = warpSum(s);
    if ((tid & 31) == 0) red[tid >> 5] = s;
    __syncthreads();
    if (tid < 32) { float v = (tid < 8) ? red[tid] : 0.0f; v = warpSum(v); if (tid == 0) red[0] = v; }
    __syncthreads();
    const float inv = 1.0f / red[0];
    for (int i = tid; i < NKr; i += 256) p[i] *= inv;
    for (int i = NKr + tid; i < NKp; i += 256) p[i] = 0.0f;
}

// ---------------- BN stats over d_wy (B,C,NQ) ----------------
__global__ void bn_stats_kernel()
{
    const int c = blockIdx.x, tid = threadIdx.x;
    float s = 0.0f, ss = 0.0f;
    for (int b = 0; b < BB; b++) {
        const float* p = d_wy + ((size_t)b * CC + c) * NQ;
        for (int i = tid; i < NQ; i += 256) { float v = p[i]; s += v; ss += v * v; }
    }
    __shared__ float r1[8], r2[8];
    s = warpSum(s); ss = warpSum(ss);
    if ((tid & 31) == 0) { r1[tid >> 5] = s; r2[tid >> 5] = ss; }
    __syncthreads();
    if (tid < 32) {
        float a  = (tid < 8) ? r1[tid] : 0.0f;
        float b2 = (tid < 8) ? r2[tid] : 0.0f;
        a = warpSum(a); b2 = warpSum(b2);
        if (tid == 0) {
            const float cnt = (float)((long long)BB * NQ);
            float mean = a / cnt;
            float var = b2 / cnt - mean * mean;
            d_mean[c] = mean;
            d_istd[c] = rsqrtf(var + BN_EPS);
        }
    }
}

__global__ void bn_apply_kernel(const float* __restrict__ x,
                                const float* __restrict__ gamma,
                                const float* __restrict__ beta,
                                float* __restrict__ out)
{
    size_t i = (size_t)blockIdx.x * 256 + threadIdx.x;
    if (i >= (size_t)BB * CC * NQ) return;
    int c = (int)((i / NQ) % CC);
    out[i] = (d_wy[i] - d_mean[c]) * d_istd[c] * gamma[c] + beta[c] + x[i];
}

// ---------------- host ----------------
extern "C" void kernel_launch(void* const* d_in, const int* in_sizes, int n_in,
                              void* d_out, int out_size)
{
    (void)in_sizes; (void)n_in; (void)out_size;
    const float* x       = (const float*)d_in[0];
    const float* theta_w = (const float*)d_in[1];
    const float* theta_b = (const float*)d_in[2];
    const float* phi_w   = (const float*)d_in[3];
    const float* phi_b   = (const float*)d_in[4];
    const float* g_w     = (const float*)d_in[5];
    const float* g_b     = (const float*)d_in[6];
    const float* w_w     = (const float*)d_in[7];
    const float* w_b     = (const float*)d_in[8];
    const float* bn_g    = (const float*)d_in[9];
    const float* bn_b    = (const float*)d_in[10];
    float* out = (float*)d_out;

    cudaFuncSetAttribute(gemm_tn, cudaFuncAttributeMaxDynamicSharedMemorySize, GEMM_SMEM);

    void *p_xt, *p_xpt, *p_th, *p_ph, *p_g2, *p_f, *p_y, *p_wy;
    cudaGetSymbolAddress(&p_xt, d_xt);
    cudaGetSymbolAddress(&p_xpt, d_xpt);
    cudaGetSymbolAddress(&p_th, d_th);
    cudaGetSymbolAddress(&p_ph, d_ph);
    cudaGetSymbolAddress(&p_g2, d_g2);
    cudaGetSymbolAddress(&p_f, d_f);
    cudaGetSymbolAddress(&p_y, d_y);
    cudaGetSymbolAddress(&p_wy, d_wy);

    const float fscale = 1.0f / sqrtf((float)CI);

    transpose_x<<<dim3(NQ/32, CC/32, BB), dim3(32,8)>>>(x);
    pool_kernel<<<dim3(NKp, BB), 256>>>();

    // theta (B,NQ,CI) = xt @ theta_w^T + theta_b[n]
    gemm_tn<<<dim3(CI/128, NQ/128, BB), 256, GEMM_SMEM>>>(
        (const float*)p_xt, theta_w, (float*)p_th,
        CC, CC, CC, CI, (long long)NQ*CC, 0LL, (long long)NQ*CI,
        nullptr, theta_b, 1.0f);
    // phi (B,NKp,CI) = xpt @ phi_w^T + phi_b[n]
    gemm_tn<<<dim3(CI/128, NKp/128, BB), 256, GEMM_SMEM>>>(
        (const float*)p_xpt, phi_w, (float*)p_ph,
        CC, CC, CC, CI, (long long)NKp*CC, 0LL, (long long)NKp*CI,
        nullptr, phi_b, 1.0f);
    // g2 (B,CI,NKp) = g_w @ xpt^T + g_b[m]
    gemm_tn<<<dim3(NKp/128, CI/128, BB), 256, GEMM_SMEM>>>(
        g_w, (const float*)p_xpt, (float*)p_g2,
        CC, CC, CC, NKp, 0LL, (long long)NKp*CC, (long long)CI*NKp,
        g_b, nullptr, 1.0f);
    // f (B,NQ,NKp) = theta @ phi^T * scale
    gemm_tn<<<dim3(NKp/128, NQ/128, BB), 256, GEMM_SMEM>>>(
        (const float*)p_th, (const float*)p_ph, (float*)p_f,
        CI, CI, CI, NKp, (long long)NQ*CI, (long long)NKp*CI, (long long)NQ*NKp,
        nullptr, nullptr, fscale);

    softmax_kernel<<<BB*NQ, 256>>>();

    // y (B,NQ,CI) = attn @ g2^T
    gemm_tn<<<dim3(CI/128, NQ/128, BB), 256, GEMM_SMEM>>>(
        (const float*)p_f, (const float*)p_g2, (float*)p_y,
        NKp, NKp, NKp, CI, (long long)NQ*NKp, (long long)CI*NKp, (long long)NQ*CI,
        nullptr, nullptr, 1.0f);
    // wy (B,CC,NQ) = w_w @ y^T + w_b[m]
    gemm_tn<<<dim3(NQ/128, CC/128, BB), 256, GEMM_SMEM>>>(
        w_w, (const float*)p_y, (float*)p_wy,
        CI, CI, CI, NQ, 0LL, (long long)NQ*CI, (long long)CC*NQ,
        w_b, nullptr, 1.0f);

    bn_stats_kernel<<<CC, 256>>>();
    {
        size_t tot = (size_t)BB * CC * NQ;
        bn_apply_kernel<<<(unsigned)((tot + 255) / 256), 256>>>(x, bn_g, bn_b, out);
    }
}

// round 5
// speedup vs baseline: 4.2055x; 1.2205x over previous
#include <cuda_runtime.h>
#include <math.h>
#include <stdint.h>

#define BB 4
#define CC 1024
#define CI 512
#define TT 16
#define HH 28
#define WW 28
#define NQ 12544
#define NKr 3136
#define NKp 3200
#define BN_EPS 1e-5f

// ---------------- scratch ----------------
__device__ __align__(256) float d_xt [(size_t)BB*NQ*CC];
__device__ __align__(256) float d_xpt[(size_t)BB*NKp*CC];
__device__ __align__(256) float d_th [(size_t)BB*NQ*CI];
__device__ __align__(256) float d_ph [(size_t)BB*NKp*CI];
__device__ __align__(256) float d_g2 [(size_t)BB*CI*NKp];
__device__ __align__(256) float d_f  [(size_t)BB*NQ*NKp];
__device__ __align__(256) float d_y  [(size_t)BB*NQ*CI];
__device__ __align__(256) float d_wy [(size_t)BB*CC*NQ];
__device__ float d_mean[CC];
__device__ float d_istd[CC];

// ---------------- helpers ----------------
__device__ __forceinline__ uint32_t s2u(const void* p) {
    uint32_t a;
    asm("{ .reg .u64 t; cvta.to.shared.u64 t, %1; cvt.u32.u64 %0, t; }" : "=r"(a) : "l"(p));
    return a;
}
__device__ __forceinline__ float warpMax(float v) {
    #pragma unroll
    for (int o = 16; o > 0; o >>= 1) v = fmaxf(v, __shfl_xor_sync(0xffffffffu, v, o));
    return v;
}
__device__ __forceinline__ float warpSum(float v) {
    #pragma unroll
    for (int o = 16; o > 0; o >>= 1) v += __shfl_xor_sync(0xffffffffu, v, o);
    return v;
}

// ---------------- tf32 mma.sync TN GEMM ----------------
// D[M,N] = scale * A[M,K] @ B[N,K]^T (+ biasM[m]) (+ biasN[n])
// M,N multiples of 128 (grid), K multiple of 32. grid=(N/128, M/128, batch)
#define LDS_P 36                       // padded row length (floats)
#define STG   (2*128*LDS_P)            // floats per stage (A tile + B tile)
#define NSTAGE 3
#define GEMM_SMEM (NSTAGE*STG*4)       // 110592 bytes -> 2 CTAs/SM

__global__ __launch_bounds__(256, 2)
void gemm_tn(const float* __restrict__ A, const float* __restrict__ B,
             float* __restrict__ D, int K, int lda, int ldb, int ldd,
             long long sA, long long sB, long long sD,
             const float* __restrict__ biasM, const float* __restrict__ biasN,
             float scale)
{
    extern __shared__ float smem[];
    const uint32_t smem_b = s2u(smem);
    const int tid = threadIdx.x, wid = tid >> 5, lane = tid & 31;
    const int wm = wid >> 2, wn = wid & 3;        // warp tile: 64 x 32
    const int g = lane >> 2, tg = lane & 3;
    const int m0 = blockIdx.y << 7, n0 = blockIdx.x << 7;
    A += (long long)blockIdx.z * sA + (size_t)m0 * lda;
    B += (long long)blockIdx.z * sB + (size_t)n0 * ldb;
    D += (long long)blockIdx.z * sD;
    const int ktiles = K >> 5;

    // producer mapping: 1024 chunks of 16B per tile; thread handles 4 chunks
    const int prow[4] = { (tid + 0) >> 3, (tid + 256) >> 3, (tid + 512) >> 3, (tid + 768) >> 3 };
    const int pc = tid & 7;

    // ldmatrix per-lane byte offsets (within a stage)
    // A frag (m16k8): tiles rows0-7/k0, rows8-15/k0, rows0-7/k4, rows8-15/k4
    const uint32_t aoff = ((uint32_t)(wm * 64 + (lane & 15)) * LDS_P + ((lane >> 4) << 2)) * 4;
    // B frags for two n-tiles per x4: lanes<16 -> nt even, lanes>=16 -> nt odd
    const uint32_t boff = ((uint32_t)(128 * LDS_P)
                          + (uint32_t)(wn * 32 + ((lane >> 4) << 3) + (lane & 7)) * LDS_P
                          + (((lane >> 3) & 1) << 2)) * 4;

    float acc[4][4][4];
    #pragma unroll
    for (int i = 0; i < 4; i++)
        #pragma unroll
        for (int j = 0; j < 4; j++)
            #pragma unroll
            for (int q = 0; q < 4; q++) acc[i][j][q] = 0.0f;

    // prologue: fill stages 0..NSTAGE-2
    #pragma unroll
    for (int s = 0; s < NSTAGE - 1; s++) {
        const float* Ab = A + (s << 5) + (pc << 2);
        const float* Bb = B + (s << 5) + (pc << 2);
        uint32_t Sa = smem_b + s * (STG * 4) + pc * 16;
        uint32_t Sb = Sa + 128 * LDS_P * 4;
        #pragma unroll
        for (int l = 0; l < 4; l++) {
            asm volatile("cp.async.cg.shared.global [%0], [%1], 16;"
                         :: "r"(Sa + prow[l] * (LDS_P*4)), "l"(Ab + (size_t)prow[l] * lda));
            asm volatile("cp.async.cg.shared.global [%0], [%1], 16;"
                         :: "r"(Sb + prow[l] * (LDS_P*4)), "l"(Bb + (size_t)prow[l] * ldb));
        }
        asm volatile("cp.async.commit_group;");
    }

    int sc = 0;                 // compute stage
    for (int kt = 0; kt < ktiles; kt++) {
        // prefetch stage kt+NSTAGE-1
        const int pf = kt + NSTAGE - 1;
        if (pf < ktiles) {
            int sp = sc + NSTAGE - 1; if (sp >= NSTAGE) sp -= NSTAGE;
            const float* Ab = A + (pf << 5) + (pc << 2);
            const float* Bb = B + (pf << 5) + (pc << 2);
            uint32_t Sa = smem_b + sp * (STG * 4) + pc * 16;
            uint32_t Sb = Sa + 128 * LDS_P * 4;
            #pragma unroll
            for (int l = 0; l < 4; l++) {
                asm volatile("cp.async.cg.shared.global [%0], [%1], 16;"
                             :: "r"(Sa + prow[l] * (LDS_P*4)), "l"(Ab + (size_t)prow[l] * lda));
                asm volatile("cp.async.cg.shared.global [%0], [%1], 16;"
                             :: "r"(Sb + prow[l] * (LDS_P*4)), "l"(Bb + (size_t)prow[l] * ldb));
            }
        }
        asm volatile("cp.async.commit_group;");
        asm volatile("cp.async.wait_group %0;" :: "n"(NSTAGE - 2));
        __syncthreads();

        const uint32_t sbase = smem_b + sc * (STG * 4);
        const uint32_t aB = sbase + aoff;
        const uint32_t bB = sbase + boff;

        #pragma unroll
        for (int ks = 0; ks < 4; ks++) {
            const uint32_t kb = ks * 32;           // 8 floats
            uint32_t a[4][4], b[4][2];
            #pragma unroll
            for (int mt = 0; mt < 4; mt++)
                asm volatile("ldmatrix.sync.aligned.m8n8.x4.shared.b16 {%0,%1,%2,%3}, [%4];"
                             : "=r"(a[mt][0]), "=r"(a[mt][1]), "=r"(a[mt][2]), "=r"(a[mt][3])
                             : "r"(aB + mt * (16 * LDS_P * 4) + kb));
            asm volatile("ldmatrix.sync.aligned.m8n8.x4.shared.b16 {%0,%1,%2,%3}, [%4];"
                         : "=r"(b[0][0]), "=r"(b[0][1]), "=r"(b[1][0]), "=r"(b[1][1])
                         : "r"(bB + kb));
            asm volatile("ldmatrix.sync.aligned.m8n8.x4.shared.b16 {%0,%1,%2,%3}, [%4];"
                         : "=r"(b[2][0]), "=r"(b[2][1]), "=r"(b[3][0]), "=r"(b[3][1])
                         : "r"(bB + 16 * (LDS_P * 4) + kb));
            #pragma unroll
            for (int mt = 0; mt < 4; mt++)
                #pragma unroll
                for (int nt = 0; nt < 4; nt++)
                    asm("mma.sync.aligned.m16n8k8.row.col.f32.tf32.tf32.f32 "
                        "{%0,%1,%2,%3}, {%4,%5,%6,%7}, {%8,%9}, {%0,%1,%2,%3};"
                        : "+f"(acc[mt][nt][0]), "+f"(acc[mt][nt][1]),
                          "+f"(acc[mt][nt][2]), "+f"(acc[mt][nt][3])
                        : "r"(a[mt][0]), "r"(a[mt][1]), "r"(a[mt][2]), "r"(a[mt][3]),
                          "r"(b[nt][0]), "r"(b[nt][1]));
        }
        __syncthreads();
        if (++sc == NSTAGE) sc = 0;
    }

    // epilogue
    #pragma unroll
    for (int mt = 0; mt < 4; mt++) {
        const int r0 = m0 + wm * 64 + mt * 16 + g;
        const float bm0 = biasM ? biasM[r0] : 0.0f;
        const float bm1 = biasM ? biasM[r0 + 8] : 0.0f;
        #pragma unroll
        for (int nt = 0; nt < 4; nt++) {
            const int col = n0 + wn * 32 + nt * 8 + tg * 2;
            const float bn0 = biasN ? biasN[col] : 0.0f;
            const float bn1 = biasN ? biasN[col + 1] : 0.0f;
            float2 v0, v1;
            v0.x = acc[mt][nt][0] * scale + bm0 + bn0;
            v0.y = acc[mt][nt][1] * scale + bm0 + bn1;
            v1.x = acc[mt][nt][2] * scale + bm1 + bn0;
            v1.y = acc[mt][nt][3] * scale + bm1 + bn1;
            *(float2*)(D + (size_t)r0 * ldd + col) = v0;
            *(float2*)(D + (size_t)(r0 + 8) * ldd + col) = v1;
        }
    }
}

// ---------------- transpose x (B,C,NQ) -> xt (B,NQ,C) ----------------
__global__ void transpose_x(const float* __restrict__ x)
{
    __shared__ float t[32][33];
    const int b = blockIdx.z;
    const int n0 = blockIdx.x << 5, c0 = blockIdx.y << 5;
    const int tx = threadIdx.x, ty = threadIdx.y;
    const float* xp = x + (size_t)b * CC * NQ;
    float* xo = d_xt + (size_t)b * NQ * CC;
    #pragma unroll
    for (int i = 0; i < 4; i++)
        t[ty + i*8][tx] = xp[(size_t)(c0 + ty + i*8) * NQ + n0 + tx];
    __syncthreads();
    #pragma unroll
    for (int i = 0; i < 4; i++)
        xo[(size_t)(n0 + ty + i*8) * CC + c0 + tx] = t[tx][ty + i*8];
}

// ---------------- pool xt -> xpt (B,NKp,C), pad rows zero ----------------
__global__ void pool_kernel()
{
    const int b = blockIdx.y, nk = blockIdx.x;
    float* o = d_xpt + ((size_t)b * NKp + nk) * CC;
    if (nk >= NKr) {
        for (int c = threadIdx.x; c < CC; c += 256) o[c] = 0.0f;
        return;
    }
    const int wi = nk % 14, hi = (nk / 14) % 14, t = nk / 196;
    const float* r0 = d_xt + ((size_t)b * NQ + (size_t)(t * HH + 2 * hi) * WW + 2 * wi) * CC;
    for (int c = threadIdx.x; c < CC; c += 256)
        o[c] = fmaxf(fmaxf(r0[c], r0[CC + c]), fmaxf(r0[(size_t)WW*CC + c], r0[(size_t)(WW+1)*CC + c]));
}

// ---------------- softmax rows of d_f (len NKp, valid NKr), zero pads ------
__global__ void softmax_kernel()
{
    float* p = d_f + (size_t)blockIdx.x * NKp;
    const int tid = threadIdx.x;
    __shared__ float red[8];
    float m = -1e30f;
    for (int i = tid; i < NKr; i += 256) m = fmaxf(m, p[i]);
    m = warpMax(m);
    if ((tid & 31) == 0) red[tid >> 5] = m;
    __syncthreads();
    if (tid < 32) { float v = (tid < 8) ? red[tid] : -1e30f; v = warpMax(v); if (tid == 0) red[0] = v; }
    __syncthreads();
    const float bm = red[0];
    __syncthreads();
    float s = 0.0f;
    for (int i = tid; i < NKr; i += 256) { float e = __expf(p[i] - bm); p[i] = e; s += e; }
    s = warpSum(s);
    if ((tid & 31) == 0) red[tid >> 5] = s;
    __syncthreads();
    if (tid < 32) { float v = (tid < 8) ? red[tid] : 0.0f; v = warpSum(v); if (tid == 0) red[0] = v; }
    __syncthreads();
    const float inv = 1.0f / red[0];
    for (int i = tid; i < NKr; i += 256) p[i] *= inv;
    for (int i = NKr + tid; i < NKp; i += 256) p[i] = 0.0f;
}

// ---------------- BN stats over d_wy (B,C,NQ) ----------------
__global__ void bn_stats_kernel()
{
    const int c = blockIdx.x, tid = threadIdx.x;
    float s = 0.0f, ss = 0.0f;
    for (int b = 0; b < BB; b++) {
        const float* p = d_wy + ((size_t)b * CC + c) * NQ;
        for (int i = tid; i < NQ; i += 256) { float v = p[i]; s += v; ss += v * v; }
    }
    __shared__ float r1[8], r2[8];
    s = warpSum(s); ss = warpSum(ss);
    if ((tid & 31) == 0) { r1[tid >> 5] = s; r2[tid >> 5] = ss; }
    __syncthreads();
    if (tid < 32) {
        float a  = (tid < 8) ? r1[tid] : 0.0f;
        float b2 = (tid < 8) ? r2[tid] : 0.0f;
        a = warpSum(a); b2 = warpSum(b2);
        if (tid == 0) {
            const float cnt = (float)((long long)BB * NQ);
            float mean = a / cnt;
            float var = b2 / cnt - mean * mean;
            d_mean[c] = mean;
            d_istd[c] = rsqrtf(var + BN_EPS);
        }
    }
}

__global__ void bn_apply_kernel(const float* __restrict__ x,
                                const float* __restrict__ gamma,
                                const float* __restrict__ beta,
                                float* __restrict__ out)
{
    size_t i = (size_t)blockIdx.x * 256 + threadIdx.x;
    if (i >= (size_t)BB * CC * NQ) return;
    int c = (int)((i / NQ) % CC);
    out[i] = (d_wy[i] - d_mean[c]) * d_istd[c] * gamma[c] + beta[c] + x[i];
}

// ---------------- host ----------------
extern "C" void kernel_launch(void* const* d_in, const int* in_sizes, int n_in,
                              void* d_out, int out_size)
{
    (void)in_sizes; (void)n_in; (void)out_size;
    const float* x       = (const float*)d_in[0];
    const float* theta_w = (const float*)d_in[1];
    const float* theta_b = (const float*)d_in[2];
    const float* phi_w   = (const float*)d_in[3];
    const float* phi_b   = (const float*)d_in[4];
    const float* g_w     = (const float*)d_in[5];
    const float* g_b     = (const float*)d_in[6];
    const float* w_w     = (const float*)d_in[7];
    const float* w_b     = (const float*)d_in[8];
    const float* bn_g    = (const float*)d_in[9];
    const float* bn_b    = (const float*)d_in[10];
    float* out = (float*)d_out;

    cudaFuncSetAttribute(gemm_tn, cudaFuncAttributeMaxDynamicSharedMemorySize, GEMM_SMEM);

    void *p_xt, *p_xpt, *p_th, *p_ph, *p_g2, *p_f, *p_y, *p_wy;
    cudaGetSymbolAddress(&p_xt, d_xt);
    cudaGetSymbolAddress(&p_xpt, d_xpt);
    cudaGetSymbolAddress(&p_th, d_th);
    cudaGetSymbolAddress(&p_ph, d_ph);
    cudaGetSymbolAddress(&p_g2, d_g2);
    cudaGetSymbolAddress(&p_f, d_f);
    cudaGetSymbolAddress(&p_y, d_y);
    cudaGetSymbolAddress(&p_wy, d_wy);

    const float fscale = 1.0f / sqrtf((float)CI);

    transpose_x<<<dim3(NQ/32, CC/32, BB), dim3(32,8)>>>(x);
    pool_kernel<<<dim3(NKp, BB), 256>>>();

    // theta (B,NQ,CI) = xt @ theta_w^T + theta_b[n]
    gemm_tn<<<dim3(CI/128, NQ/128, BB), 256, GEMM_SMEM>>>(
        (const float*)p_xt, theta_w, (float*)p_th,
        CC, CC, CC, CI, (long long)NQ*CC, 0LL, (long long)NQ*CI,
        nullptr, theta_b, 1.0f);
    // phi (B,NKp,CI) = xpt @ phi_w^T + phi_b[n]
    gemm_tn<<<dim3(CI/128, NKp/128, BB), 256, GEMM_SMEM>>>(
        (const float*)p_xpt, phi_w, (float*)p_ph,
        CC, CC, CC, CI, (long long)NKp*CC, 0LL, (long long)NKp*CI,
        nullptr, phi_b, 1.0f);
    // g2 (B,CI,NKp) = g_w @ xpt^T + g_b[m]
    gemm_tn<<<dim3(NKp/128, CI/128, BB), 256, GEMM_SMEM>>>(
        g_w, (const float*)p_xpt, (float*)p_g2,
        CC, CC, CC, NKp, 0LL, (long long)NKp*CC, (long long)CI*NKp,
        g_b, nullptr, 1.0f);
    // f (B,NQ,NKp) = theta @ phi^T * scale
    gemm_tn<<<dim3(NKp/128, NQ/128, BB), 256, GEMM_SMEM>>>(
        (const float*)p_th, (const float*)p_ph, (float*)p_f,
        CI, CI, CI, NKp, (long long)NQ*CI, (long long)NKp*CI, (long long)NQ*NKp,
        nullptr, nullptr, fscale);

    softmax_kernel<<<BB*NQ, 256>>>();

    // y (B,NQ,CI) = attn @ g2^T
    gemm_tn<<<dim3(CI/128, NQ/128, BB), 256, GEMM_SMEM>>>(
        (const float*)p_f, (const float*)p_g2, (float*)p_y,
        NKp, NKp, NKp, CI, (long long)NQ*NKp, (long long)CI*NKp, (long long)NQ*CI,
        nullptr, nullptr, 1.0f);
    // wy (B,CC,NQ) = w_w @ y^T + w_b[m]
    gemm_tn<<<dim3(NQ/128, CC/128, BB), 256, GEMM_SMEM>>>(
        w_w, (const float*)p_y, (float*)p_wy,
        CI, CI, CI, NQ, 0LL, (long long)NQ*CI, (long long)CC*NQ,
        w_b, nullptr, 1.0f);

    bn_stats_kernel<<<CC, 256>>>();
    {
        size_t tot = (size_t)BB * CC * NQ;
        bn_apply_kernel<<<(unsigned)((tot + 255) / 256), 256>>>(x, bn_g, bn_b, out);
    }
}

// round 6
// speedup vs baseline: 5.9391x; 1.4122x over previous
#include <cuda_runtime.h>
#include <cuda_fp16.h>
#include <math.h>
#include <stdint.h>

#define BB 4
#define CC 1024
#define CI 512
#define TT 16
#define HH 28
#define WW 28
#define NQ 12544
#define NKr 3136
#define NKp 3200
#define BN_EPS 1e-5f

// ---------------- scratch ----------------
__device__ __align__(256) __half d_xt  [(size_t)BB*NQ*CC];
__device__ __align__(256) __half d_xpt [(size_t)BB*NKp*CC];
__device__ __align__(256) __half d_th  [(size_t)BB*NQ*CI];
__device__ __align__(256) __half d_ph  [(size_t)BB*NKp*CI];
__device__ __align__(256) __half d_g2  [(size_t)BB*CI*NKp];
__device__ __align__(256) float  d_f   [(size_t)BB*NQ*NKp];
__device__ __align__(256) __half d_attn[(size_t)BB*NQ*NKp];
__device__ __align__(256) __half d_y   [(size_t)BB*NQ*CI];
__device__ __align__(256) float  d_wy  [(size_t)BB*CC*NQ];
__device__ __align__(256) __half d_thw [CI*CC];
__device__ __align__(256) __half d_phw [CI*CC];
__device__ __align__(256) __half d_gw  [CI*CC];
__device__ __align__(256) __half d_ww  [CC*CI];
__device__ float d_mean[CC];
__device__ float d_istd[CC];

// ---------------- helpers ----------------
__device__ __forceinline__ uint32_t s2u(const void* p) {
    uint32_t a;
    asm("{ .reg .u64 t; cvta.to.shared.u64 t, %1; cvt.u32.u64 %0, t; }" : "=r"(a) : "l"(p));
    return a;
}
__device__ __forceinline__ float warpMax(float v) {
    #pragma unroll
    for (int o = 16; o > 0; o >>= 1) v = fmaxf(v, __shfl_xor_sync(0xffffffffu, v, o));
    return v;
}
__device__ __forceinline__ float warpSum(float v) {
    #pragma unroll
    for (int o = 16; o > 0; o >>= 1) v += __shfl_xor_sync(0xffffffffu, v, o);
    return v;
}
__device__ __forceinline__ void st2(float* p, float a, float b) {
    *(float2*)p = make_float2(a, b);
}
__device__ __forceinline__ void st2(__half* p, float a, float b) {
    *(__half2*)p = __floats2half2_rn(a, b);
}

// ---------------- fp16 mma.sync TN GEMM ----------------
// D[M,N] = scale * A[M,K] @ B[N,K]^T (+ biasM[m]) (+ biasN[n])
// A,B fp16 K-major; M,N multiples of 128 (grid), K multiple of 32.
// grid=(N/128, M/128, batch), block=256 (8 warps, each 64x32)
#define LDS_PH 40                      // halfs per row (64B data + 16B pad)
#define ROW_B  (LDS_PH*2)              // 80 bytes
#define TILE_B (128*ROW_B)             // 10240 bytes per tile
#define STG_B  (2*TILE_B)              // 20480 bytes per stage
#define NSTAGE 4
#define GEMM_SMEM (NSTAGE*STG_B)       // 81920 -> 2 CTAs/SM

template<typename TO>
__global__ __launch_bounds__(256, 2)
void gemm_tn(const __half* __restrict__ A, const __half* __restrict__ B,
             TO* __restrict__ D, int K, int lda, int ldb, int ldd,
             long long sA, long long sB, long long sD,
             const float* __restrict__ biasM, const float* __restrict__ biasN,
             float scale)
{
    extern __shared__ char smem[];
    const uint32_t smem_b = s2u(smem);
    const int tid = threadIdx.x, wid = tid >> 5, lane = tid & 31;
    const int wm = wid >> 2, wn = wid & 3;        // warp tile: 64 x 32
    const int g = lane >> 2, tg = lane & 3;
    const int m0 = blockIdx.y << 7, n0 = blockIdx.x << 7;
    A += (long long)blockIdx.z * sA + (size_t)m0 * lda;
    B += (long long)blockIdx.z * sB + (size_t)n0 * ldb;
    D += (long long)blockIdx.z * sD;
    const int ktiles = K >> 5;

    // producer: tile = 128 rows x 4 chunks(16B); thread does chunks {tid, tid+256} per tile
    const int pr0 = tid >> 2, pr1 = (tid + 256) >> 2;
    const int pc = tid & 3;

    // ldmatrix byte offsets within a stage
    const uint32_t aoff = (uint32_t)(wm * 64 + (lane & 15)) * ROW_B + ((lane >> 4) << 4);
    const uint32_t boff = (uint32_t)TILE_B
                        + (uint32_t)(wn * 32 + ((lane >> 4) << 3) + (lane & 7)) * ROW_B
                        + (((lane >> 3) & 1) << 4);

    float acc[4][4][4];
    #pragma unroll
    for (int i = 0; i < 4; i++)
        #pragma unroll
        for (int j = 0; j < 4; j++)
            #pragma unroll
            for (int q = 0; q < 4; q++) acc[i][j][q] = 0.0f;

    // prologue: stages 0..NSTAGE-2
    #pragma unroll
    for (int s = 0; s < NSTAGE - 1; s++) {
        const __half* Ab = A + (s << 5) + (pc << 3);
        const __half* Bb = B + (s << 5) + (pc << 3);
        uint32_t Sa = smem_b + s * STG_B + pc * 16;
        uint32_t Sb = Sa + TILE_B;
        asm volatile("cp.async.cg.shared.global [%0], [%1], 16;"
                     :: "r"(Sa + pr0 * ROW_B), "l"(Ab + (size_t)pr0 * lda));
        asm volatile("cp.async.cg.shared.global [%0], [%1], 16;"
                     :: "r"(Sa + pr1 * ROW_B), "l"(Ab + (size_t)pr1 * lda));
        asm volatile("cp.async.cg.shared.global [%0], [%1], 16;"
                     :: "r"(Sb + pr0 * ROW_B), "l"(Bb + (size_t)pr0 * ldb));
        asm volatile("cp.async.cg.shared.global [%0], [%1], 16;"
                     :: "r"(Sb + pr1 * ROW_B), "l"(Bb + (size_t)pr1 * ldb));
        asm volatile("cp.async.commit_group;");
    }

    int sc = 0;
    for (int kt = 0; kt < ktiles; kt++) {
        const int pf = kt + NSTAGE - 1;
        if (pf < ktiles) {
            int sp = sc + NSTAGE - 1; if (sp >= NSTAGE) sp -= NSTAGE;
            const __half* Ab = A + (pf << 5) + (pc << 3);
            const __half* Bb = B + (pf << 5) + (pc << 3);
            uint32_t Sa = smem_b + sp * STG_B + pc * 16;
            uint32_t Sb = Sa + TILE_B;
            asm volatile("cp.async.cg.shared.global [%0], [%1], 16;"
                         :: "r"(Sa + pr0 * ROW_B), "l"(Ab + (size_t)pr0 * lda));
            asm volatile("cp.async.cg.shared.global [%0], [%1], 16;"
                         :: "r"(Sa + pr1 * ROW_B), "l"(Ab + (size_t)pr1 * lda));
            asm volatile("cp.async.cg.shared.global [%0], [%1], 16;"
                         :: "r"(Sb + pr0 * ROW_B), "l"(Bb + (size_t)pr0 * ldb));
            asm volatile("cp.async.cg.shared.global [%0], [%1], 16;"
                         :: "r"(Sb + pr1 * ROW_B), "l"(Bb + (size_t)pr1 * ldb));
        }
        asm volatile("cp.async.commit_group;");
        asm volatile("cp.async.wait_group %0;" :: "n"(NSTAGE - 2));
        __syncthreads();

        const uint32_t sbase = smem_b + sc * STG_B;
        const uint32_t aB = sbase + aoff;
        const uint32_t bB = sbase + boff;

        #pragma unroll
        for (int ks = 0; ks < 2; ks++) {
            const uint32_t kb = ks * 32;           // 16 halfs
            uint32_t a[4][4], b[4][2];
            #pragma unroll
            for (int mt = 0; mt < 4; mt++)
                asm volatile("ldmatrix.sync.aligned.m8n8.x4.shared.b16 {%0,%1,%2,%3}, [%4];"
                             : "=r"(a[mt][0]), "=r"(a[mt][1]), "=r"(a[mt][2]), "=r"(a[mt][3])
                             : "r"(aB + mt * (16 * ROW_B) + kb));
            asm volatile("ldmatrix.sync.aligned.m8n8.x4.shared.b16 {%0,%1,%2,%3}, [%4];"
                         : "=r"(b[0][0]), "=r"(b[0][1]), "=r"(b[1][0]), "=r"(b[1][1])
                         : "r"(bB + kb));
            asm volatile("ldmatrix.sync.aligned.m8n8.x4.shared.b16 {%0,%1,%2,%3}, [%4];"
                         : "=r"(b[2][0]), "=r"(b[2][1]), "=r"(b[3][0]), "=r"(b[3][1])
                         : "r"(bB + 16 * ROW_B + kb));
            #pragma unroll
            for (int mt = 0; mt < 4; mt++)
                #pragma unroll
                for (int nt = 0; nt < 4; nt++)
                    asm("mma.sync.aligned.m16n8k16.row.col.f32.f16.f16.f32 "
                        "{%0,%1,%2,%3}, {%4,%5,%6,%7}, {%8,%9}, {%0,%1,%2,%3};"
                        : "+f"(acc[mt][nt][0]), "+f"(acc[mt][nt][1]),
                          "+f"(acc[mt][nt][2]), "+f"(acc[mt][nt][3])
                        : "r"(a[mt][0]), "r"(a[mt][1]), "r"(a[mt][2]), "r"(a[mt][3]),
                          "r"(b[nt][0]), "r"(b[nt][1]));
        }
        __syncthreads();
        if (++sc == NSTAGE) sc = 0;
    }

    // epilogue
    #pragma unroll
    for (int mt = 0; mt < 4; mt++) {
        const int r0 = m0 + wm * 64 + mt * 16 + g;
        const float bm0 = biasM ? biasM[r0] : 0.0f;
        const float bm1 = biasM ? biasM[r0 + 8] : 0.0f;
        #pragma unroll
        for (int nt = 0; nt < 4; nt++) {
            const int col = n0 + wn * 32 + nt * 8 + tg * 2;
            const float bn0 = biasN ? biasN[col] : 0.0f;
            const float bn1 = biasN ? biasN[col + 1] : 0.0f;
            st2(D + (size_t)r0 * ldd + col,
                acc[mt][nt][0] * scale + bm0 + bn0,
                acc[mt][nt][1] * scale + bm0 + bn1);
            st2(D + (size_t)(r0 + 8) * ldd + col,
                acc[mt][nt][2] * scale + bm1 + bn0,
                acc[mt][nt][3] * scale + bm1 + bn1);
        }
    }
}

// ---------------- fp32 -> fp16 convert ----------------
__global__ void f2h_kernel(const float* __restrict__ s, __half* __restrict__ d, int n)
{
    int i = blockIdx.x * 256 + threadIdx.x;
    if (2 * i < n) {
        float2 v = *(const float2*)(s + 2 * i);
        *(__half2*)(d + 2 * i) = __floats2half2_rn(v.x, v.y);
    }
}

// ---------------- transpose x (B,C,NQ) -> xt fp16 (B,NQ,C) ----------------
__global__ void transpose_x(const float* __restrict__ x)
{
    __shared__ float t[32][33];
    const int b = blockIdx.z;
    const int n0 = blockIdx.x << 5, c0 = blockIdx.y << 5;
    const int tx = threadIdx.x, ty = threadIdx.y;
    const float* xp = x + (size_t)b * CC * NQ;
    __half* xo = d_xt + (size_t)b * NQ * CC;
    #pragma unroll
    for (int i = 0; i < 4; i++)
        t[ty + i*8][tx] = xp[(size_t)(c0 + ty + i*8) * NQ + n0 + tx];
    __syncthreads();
    #pragma unroll
    for (int i = 0; i < 4; i++)
        xo[(size_t)(n0 + ty + i*8) * CC + c0 + tx] = __float2half(t[tx][ty + i*8]);
}

// ---------------- pool xt -> xpt fp16 (B,NKp,C), pad rows zero ----------------
__global__ void pool_kernel()
{
    const int b = blockIdx.y, nk = blockIdx.x;
    __half* o = d_xpt + ((size_t)b * NKp + nk) * CC;
    if (nk >= NKr) {
        for (int c = threadIdx.x; c < CC; c += 256) o[c] = __float2half(0.0f);
        return;
    }
    const int wi = nk % 14, hi = (nk / 14) % 14, t = nk / 196;
    const __half* r0 = d_xt + ((size_t)b * NQ + (size_t)(t * HH + 2 * hi) * WW + 2 * wi) * CC;
    for (int c = threadIdx.x; c < CC; c += 256) {
        float v = fmaxf(fmaxf(__half2float(r0[c]), __half2float(r0[CC + c])),
                        fmaxf(__half2float(r0[(size_t)WW*CC + c]),
                              __half2float(r0[(size_t)(WW+1)*CC + c])));
        o[c] = __float2half(v);
    }
}

// ---------------- softmax: f fp32 -> attn fp16, pad zero ----------------
__global__ void softmax_kernel()
{
    const float* p = d_f + (size_t)blockIdx.x * NKp;
    __half* q = d_attn + (size_t)blockIdx.x * NKp;
    const int tid = threadIdx.x;
    __shared__ float red[8];
    float m = -1e30f;
    for (int i = tid; i < NKr; i += 256) m = fmaxf(m, p[i]);
    m = warpMax(m);
    if ((tid & 31) == 0) red[tid >> 5] = m;
    __syncthreads();
    if (tid < 32) { float v = (tid < 8) ? red[tid] : -1e30f; v = warpMax(v); if (tid == 0) red[0] = v; }
    __syncthreads();
    const float bm = red[0];
    __syncthreads();
    float s = 0.0f;
    for (int i = tid; i < NKr; i += 256) s += __expf(p[i] - bm);
    s = warpSum(s);
    if ((tid & 31) == 0) red[tid >> 5] = s;
    __syncthreads();
    if (tid < 32) { float v = (tid < 8) ? red[tid] : 0.0f; v = warpSum(v); if (tid == 0) red[0] = v; }
    __syncthreads();
    const float inv = 1.0f / red[0];
    for (int i = tid; i < NKr; i += 256) q[i] = __float2half(__expf(p[i] - bm) * inv);
    for (int i = NKr + tid; i < NKp; i += 256) q[i] = __float2half(0.0f);
}

// ---------------- BN stats over d_wy (B,C,NQ) ----------------
__global__ void bn_stats_kernel()
{
    const int c = blockIdx.x, tid = threadIdx.x;
    float s = 0.0f, ss = 0.0f;
    for (int b = 0; b < BB; b++) {
        const float* p = d_wy + ((size_t)b * CC + c) * NQ;
        for (int i = tid; i < NQ; i += 256) { float v = p[i]; s += v; ss += v * v; }
    }
    __shared__ float r1[8], r2[8];
    s = warpSum(s); ss = warpSum(ss);
    if ((tid & 31) == 0) { r1[tid >> 5] = s; r2[tid >> 5] = ss; }
    __syncthreads();
    if (tid < 32) {
        float a  = (tid < 8) ? r1[tid] : 0.0f;
        float b2 = (tid < 8) ? r2[tid] : 0.0f;
        a = warpSum(a); b2 = warpSum(b2);
        if (tid == 0) {
            const float cnt = (float)((long long)BB * NQ);
            float mean = a / cnt;
            float var = b2 / cnt - mean * mean;
            d_mean[c] = mean;
            d_istd[c] = rsqrtf(var + BN_EPS);
        }
    }
}

__global__ void bn_apply_kernel(const float* __restrict__ x,
                                const float* __restrict__ gamma,
                                const float* __restrict__ beta,
                                float* __restrict__ out)
{
    size_t i = (size_t)blockIdx.x * 256 + threadIdx.x;
    if (i >= (size_t)BB * CC * NQ) return;
    int c = (int)((i / NQ) % CC);
    out[i] = (d_wy[i] - d_mean[c]) * d_istd[c] * gamma[c] + beta[c] + x[i];
}

// ---------------- host ----------------
extern "C" void kernel_launch(void* const* d_in, const int* in_sizes, int n_in,
                              void* d_out, int out_size)
{
    (void)in_sizes; (void)n_in; (void)out_size;
    const float* x       = (const float*)d_in[0];
    const float* theta_w = (const float*)d_in[1];
    const float* theta_b = (const float*)d_in[2];
    const float* phi_w   = (const float*)d_in[3];
    const float* phi_b   = (const float*)d_in[4];
    const float* g_w     = (const float*)d_in[5];
    const float* g_b     = (const float*)d_in[6];
    const float* w_w     = (const float*)d_in[7];
    const float* w_b     = (const float*)d_in[8];
    const float* bn_g    = (const float*)d_in[9];
    const float* bn_b    = (const float*)d_in[10];
    float* out = (float*)d_out;

    cudaFuncSetAttribute(gemm_tn<float>,  cudaFuncAttributeMaxDynamicSharedMemorySize, GEMM_SMEM);
    cudaFuncSetAttribute(gemm_tn<__half>, cudaFuncAttributeMaxDynamicSharedMemorySize, GEMM_SMEM);

    void *p_xt, *p_xpt, *p_th, *p_ph, *p_g2, *p_f, *p_attn, *p_y, *p_wy;
    void *p_thw, *p_phw, *p_gw, *p_ww;
    cudaGetSymbolAddress(&p_xt, d_xt);
    cudaGetSymbolAddress(&p_xpt, d_xpt);
    cudaGetSymbolAddress(&p_th, d_th);
    cudaGetSymbolAddress(&p_ph, d_ph);
    cudaGetSymbolAddress(&p_g2, d_g2);
    cudaGetSymbolAddress(&p_f, d_f);
    cudaGetSymbolAddress(&p_attn, d_attn);
    cudaGetSymbolAddress(&p_y, d_y);
    cudaGetSymbolAddress(&p_wy, d_wy);
    cudaGetSymbolAddress(&p_thw, d_thw);
    cudaGetSymbolAddress(&p_phw, d_phw);
    cudaGetSymbolAddress(&p_gw, d_gw);
    cudaGetSymbolAddress(&p_ww, d_ww);

    const float fscale = 1.0f / sqrtf((float)CI);
    const int wsz = CI * CC;   // 524288

    f2h_kernel<<<wsz/512, 256>>>(theta_w, (__half*)p_thw, wsz);
    f2h_kernel<<<wsz/512, 256>>>(phi_w,   (__half*)p_phw, wsz);
    f2h_kernel<<<wsz/512, 256>>>(g_w,     (__half*)p_gw,  wsz);
    f2h_kernel<<<wsz/512, 256>>>(w_w,     (__half*)p_ww,  wsz);
    transpose_x<<<dim3(NQ/32, CC/32, BB), dim3(32,8)>>>(x);
    pool_kernel<<<dim3(NKp, BB), 256>>>();

    // theta (B,NQ,CI) = xt @ theta_w^T + theta_b[n]   -> fp16
    gemm_tn<__half><<<dim3(CI/128, NQ/128, BB), 256, GEMM_SMEM>>>(
        (const __half*)p_xt, (const __half*)p_thw, (__half*)p_th,
        CC, CC, CC, CI, (long long)NQ*CC, 0LL, (long long)NQ*CI,
        nullptr, theta_b, 1.0f);
    // phi (B,NKp,CI) = xpt @ phi_w^T + phi_b[n]       -> fp16
    gemm_tn<__half><<<dim3(CI/128, NKp/128, BB), 256, GEMM_SMEM>>>(
        (const __half*)p_xpt, (const __half*)p_phw, (__half*)p_ph,
        CC, CC, CC, CI, (long long)NKp*CC, 0LL, (long long)NKp*CI,
        nullptr, phi_b, 1.0f);
    // g2 (B,CI,NKp) = g_w @ xpt^T + g_b[m]            -> fp16
    gemm_tn<__half><<<dim3(NKp/128, CI/128, BB), 256, GEMM_SMEM>>>(
        (const __half*)p_gw, (const __half*)p_xpt, (__half*)p_g2,
        CC, CC, CC, NKp, 0LL, (long long)NKp*CC, (long long)CI*NKp,
        g_b, nullptr, 1.0f);
    // f (B,NQ,NKp) = theta @ phi^T * scale            -> fp32
    gemm_tn<float><<<dim3(NKp/128, NQ/128, BB), 256, GEMM_SMEM>>>(
        (const __half*)p_th, (const __half*)p_ph, (float*)p_f,
        CI, CI, CI, NKp, (long long)NQ*CI, (long long)NKp*CI, (long long)NQ*NKp,
        nullptr, nullptr, fscale);

    softmax_kernel<<<BB*NQ, 256>>>();

    // y (B,NQ,CI) = attn @ g2^T                        -> fp16
    gemm_tn<__half><<<dim3(CI/128, NQ/128, BB), 256, GEMM_SMEM>>>(
        (const __half*)p_attn, (const __half*)p_g2, (__half*)p_y,
        NKp, NKp, NKp, CI, (long long)NQ*NKp, (long long)CI*NKp, (long long)NQ*CI,
        nullptr, nullptr, 1.0f);
    // wy (B,CC,NQ) = w_w @ y^T + w_b[m]                -> fp32
    gemm_tn<float><<<dim3(NQ/128, CC/128, BB), 256, GEMM_SMEM>>>(
        (const __half*)p_ww, (const __half*)p_y, (float*)p_wy,
        CI, CI, CI, NQ, 0LL, (long long)NQ*CI, (long long)CC*NQ,
        w_b, nullptr, 1.0f);

    bn_stats_kernel<<<CC, 256>>>();
    {
        size_t tot = (size_t)BB * CC * NQ;
        bn_apply_kernel<<<(unsigned)((tot + 255) / 256), 256>>>(x, bn_g, bn_b, out);
    }
}

// round 7
// speedup vs baseline: 6.7350x; 1.1340x over previous
#include <cuda_runtime.h>
#include <cuda_fp16.h>
#include <math.h>
#include <stdint.h>

#define BB 4
#define CC 1024
#define CI 512
#define TT 16
#define HH 28
#define WW 28
#define NQ 12544
#define NKr 3136
#define NKp 3200
#define BN_EPS 1e-5f

// ---------------- scratch ----------------
__device__ __align__(256) __half d_xt  [(size_t)BB*NQ*CC];
__device__ __align__(256) __half d_xpt [(size_t)BB*NKp*CC];
__device__ __align__(256) __half d_th  [(size_t)BB*NQ*CI];
__device__ __align__(256) __half d_ph  [(size_t)BB*NKp*CI];
__device__ __align__(256) __half d_g2  [(size_t)BB*CI*NKp];
__device__ __align__(256) __half d_f   [(size_t)BB*NQ*NKp];
__device__ __align__(256) __half d_attn[(size_t)BB*NQ*NKp];
__device__ __align__(256) __half d_y   [(size_t)BB*NQ*CI];
__device__ __align__(256) float  d_wy  [(size_t)BB*CC*NQ];
__device__ __align__(256) __half d_thw [CI*CC];
__device__ __align__(256) __half d_phw [CI*CC];
__device__ __align__(256) __half d_gw  [CI*CC];
__device__ __align__(256) __half d_ww  [CC*CI];
__device__ float d_mean[CC];
__device__ float d_istd[CC];

// ---------------- helpers ----------------
__device__ __forceinline__ uint32_t s2u(const void* p) {
    uint32_t a;
    asm("{ .reg .u64 t; cvta.to.shared.u64 t, %1; cvt.u32.u64 %0, t; }" : "=r"(a) : "l"(p));
    return a;
}
__device__ __forceinline__ float warpMax(float v) {
    #pragma unroll
    for (int o = 16; o > 0; o >>= 1) v = fmaxf(v, __shfl_xor_sync(0xffffffffu, v, o));
    return v;
}
__device__ __forceinline__ float warpSum(float v) {
    #pragma unroll
    for (int o = 16; o > 0; o >>= 1) v += __shfl_xor_sync(0xffffffffu, v, o);
    return v;
}
__device__ __forceinline__ void st2(float* p, float a, float b) {
    *(float2*)p = make_float2(a, b);
}
__device__ __forceinline__ void st2(__half* p, float a, float b) {
    *(__half2*)p = __floats2half2_rn(a, b);
}

// ---------------- fp16 mma.sync TN GEMM, BK=64 ----------------
// D[M,N] = scale * A[M,K] @ B[N,K]^T (+ biasM[m]) (+ biasN[n])
// A,B fp16 K-major; M,N multiples of 128 (grid), K multiple of 64.
// grid=(N/128, M/128, batch), block=256 (8 warps, each 64x32)
#define ROW_B  144                     // 128B data + 16B pad
#define TILE_B (128*ROW_B)             // 18432 bytes per tile
#define STG_B  (2*TILE_B)              // 36864 bytes per stage
#define NSTAGE 3
#define GEMM_SMEM (NSTAGE*STG_B)       // 110592 -> 2 CTAs/SM

template<typename TO>
__global__ __launch_bounds__(256, 2)
void gemm_tn(const __half* __restrict__ A, const __half* __restrict__ B,
             TO* __restrict__ D, int K, int lda, int ldb, int ldd,
             long long sA, long long sB, long long sD,
             const float* __restrict__ biasM, const float* __restrict__ biasN,
             float scale)
{
    extern __shared__ char smem[];
    const uint32_t smem_b = s2u(smem);
    const int tid = threadIdx.x, wid = tid >> 5, lane = tid & 31;
    const int wm = wid >> 2, wn = wid & 3;        // warp tile: 64 x 32
    const int g = lane >> 2, tg = lane & 3;
    const int m0 = blockIdx.y << 7, n0 = blockIdx.x << 7;
    A += (long long)blockIdx.z * sA + (size_t)m0 * lda;
    B += (long long)blockIdx.z * sB + (size_t)n0 * ldb;
    D += (long long)blockIdx.z * sD;
    const int ktiles = K >> 6;

    // producer: per tile 1024 chunks of 16B (128 rows x 8); thread does 4/tile
    const int prow[4] = { (tid + 0) >> 3, (tid + 256) >> 3, (tid + 512) >> 3, (tid + 768) >> 3 };
    const int pc = tid & 7;                       // 16B chunk in row

    // ldmatrix byte offsets within a stage
    const uint32_t aoff = (uint32_t)(wm * 64 + (lane & 15)) * ROW_B + ((lane >> 4) << 4);
    const uint32_t boff = (uint32_t)TILE_B
                        + (uint32_t)(wn * 32 + ((lane >> 4) << 3) + (lane & 7)) * ROW_B
                        + (((lane >> 3) & 1) << 4);

    float acc[4][4][4];
    #pragma unroll
    for (int i = 0; i < 4; i++)
        #pragma unroll
        for (int j = 0; j < 4; j++)
            #pragma unroll
            for (int q = 0; q < 4; q++) acc[i][j][q] = 0.0f;

    // prologue: stages 0..NSTAGE-2
    #pragma unroll
    for (int s = 0; s < NSTAGE - 1; s++) {
        const __half* Ab = A + (s << 6) + (pc << 3);
        const __half* Bb = B + (s << 6) + (pc << 3);
        uint32_t Sa = smem_b + s * STG_B + pc * 16;
        uint32_t Sb = Sa + TILE_B;
        #pragma unroll
        for (int l = 0; l < 4; l++) {
            asm volatile("cp.async.cg.shared.global [%0], [%1], 16;"
                         :: "r"(Sa + prow[l] * ROW_B), "l"(Ab + (size_t)prow[l] * lda));
            asm volatile("cp.async.cg.shared.global [%0], [%1], 16;"
                         :: "r"(Sb + prow[l] * ROW_B), "l"(Bb + (size_t)prow[l] * ldb));
        }
        asm volatile("cp.async.commit_group;");
    }

    int sc = 0;
    for (int kt = 0; kt < ktiles; kt++) {
        const int pf = kt + NSTAGE - 1;
        if (pf < ktiles) {
            int sp = sc + NSTAGE - 1; if (sp >= NSTAGE) sp -= NSTAGE;
            const __half* Ab = A + (pf << 6) + (pc << 3);
            const __half* Bb = B + (pf << 6) + (pc << 3);
            uint32_t Sa = smem_b + sp * STG_B + pc * 16;
            uint32_t Sb = Sa + TILE_B;
            #pragma unroll
            for (int l = 0; l < 4; l++) {
                asm volatile("cp.async.cg.shared.global [%0], [%1], 16;"
                             :: "r"(Sa + prow[l] * ROW_B), "l"(Ab + (size_t)prow[l] * lda));
                asm volatile("cp.async.cg.shared.global [%0], [%1], 16;"
                             :: "r"(Sb + prow[l] * ROW_B), "l"(Bb + (size_t)prow[l] * ldb));
            }
        }
        asm volatile("cp.async.commit_group;");
        asm volatile("cp.async.wait_group %0;" :: "n"(NSTAGE - 2));
        __syncthreads();

        const uint32_t sbase = smem_b + sc * STG_B;
        const uint32_t aB = sbase + aoff;
        const uint32_t bB = sbase + boff;

        #pragma unroll
        for (int ks = 0; ks < 4; ks++) {
            const uint32_t kb = ks * 32;           // 16 halfs
            uint32_t a[4][4], b[4][2];
            #pragma unroll
            for (int mt = 0; mt < 4; mt++)
                asm volatile("ldmatrix.sync.aligned.m8n8.x4.shared.b16 {%0,%1,%2,%3}, [%4];"
                             : "=r"(a[mt][0]), "=r"(a[mt][1]), "=r"(a[mt][2]), "=r"(a[mt][3])
                             : "r"(aB + mt * (16 * ROW_B) + kb));
            asm volatile("ldmatrix.sync.aligned.m8n8.x4.shared.b16 {%0,%1,%2,%3}, [%4];"
                         : "=r"(b[0][0]), "=r"(b[0][1]), "=r"(b[1][0]), "=r"(b[1][1])
                         : "r"(bB + kb));
            asm volatile("ldmatrix.sync.aligned.m8n8.x4.shared.b16 {%0,%1,%2,%3}, [%4];"
                         : "=r"(b[2][0]), "=r"(b[2][1]), "=r"(b[3][0]), "=r"(b[3][1])
                         : "r"(bB + 16 * ROW_B + kb));
            #pragma unroll
            for (int mt = 0; mt < 4; mt++)
                #pragma unroll
                for (int nt = 0; nt < 4; nt++)
                    asm("mma.sync.aligned.m16n8k16.row.col.f32.f16.f16.f32 "
                        "{%0,%1,%2,%3}, {%4,%5,%6,%7}, {%8,%9}, {%0,%1,%2,%3};"
                        : "+f"(acc[mt][nt][0]), "+f"(acc[mt][nt][1]),
                          "+f"(acc[mt][nt][2]), "+f"(acc[mt][nt][3])
                        : "r"(a[mt][0]), "r"(a[mt][1]), "r"(a[mt][2]), "r"(a[mt][3]),
                          "r"(b[nt][0]), "r"(b[nt][1]));
        }
        __syncthreads();
        if (++sc == NSTAGE) sc = 0;
    }

    // epilogue
    #pragma unroll
    for (int mt = 0; mt < 4; mt++) {
        const int r0 = m0 + wm * 64 + mt * 16 + g;
        const float bm0 = biasM ? biasM[r0] : 0.0f;
        const float bm1 = biasM ? biasM[r0 + 8] : 0.0f;
        #pragma unroll
        for (int nt = 0; nt < 4; nt++) {
            const int col = n0 + wn * 32 + nt * 8 + tg * 2;
            const float bn0 = biasN ? biasN[col] : 0.0f;
            const float bn1 = biasN ? biasN[col + 1] : 0.0f;
            st2(D + (size_t)r0 * ldd + col,
                acc[mt][nt][0] * scale + bm0 + bn0,
                acc[mt][nt][1] * scale + bm0 + bn1);
            st2(D + (size_t)(r0 + 8) * ldd + col,
                acc[mt][nt][2] * scale + bm1 + bn0,
                acc[mt][nt][3] * scale + bm1 + bn1);
        }
    }
}

// ---------------- fp32 -> fp16 convert ----------------
__global__ void f2h_kernel(const float* __restrict__ s, __half* __restrict__ d, int n)
{
    int i = blockIdx.x * 256 + threadIdx.x;
    if (2 * i < n) {
        float2 v = *(const float2*)(s + 2 * i);
        *(__half2*)(d + 2 * i) = __floats2half2_rn(v.x, v.y);
    }
}

// ---------------- transpose x (B,C,NQ) -> xt fp16 (B,NQ,C) ----------------
__global__ void transpose_x(const float* __restrict__ x)
{
    __shared__ float t[32][33];
    const int b = blockIdx.z;
    const int n0 = blockIdx.x << 5, c0 = blockIdx.y << 5;
    const int tx = threadIdx.x, ty = threadIdx.y;
    const float* xp = x + (size_t)b * CC * NQ;
    __half* xo = d_xt + (size_t)b * NQ * CC;
    #pragma unroll
    for (int i = 0; i < 4; i++)
        t[ty + i*8][tx] = xp[(size_t)(c0 + ty + i*8) * NQ + n0 + tx];
    __syncthreads();
    #pragma unroll
    for (int i = 0; i < 4; i++)
        xo[(size_t)(n0 + ty + i*8) * CC + c0 + tx] = __float2half(t[tx][ty + i*8]);
}

// ---------------- pool xt -> xpt fp16 (B,NKp,C), pad rows zero ----------------
__global__ void pool_kernel()
{
    const int b = blockIdx.y, nk = blockIdx.x;
    __half* o = d_xpt + ((size_t)b * NKp + nk) * CC;
    if (nk >= NKr) {
        for (int c = threadIdx.x; c < CC; c += 256) o[c] = __float2half(0.0f);
        return;
    }
    const int wi = nk % 14, hi = (nk / 14) % 14, t = nk / 196;
    const __half* r0 = d_xt + ((size_t)b * NQ + (size_t)(t * HH + 2 * hi) * WW + 2 * wi) * CC;
    for (int c = threadIdx.x; c < CC; c += 256) {
        float v = fmaxf(fmaxf(__half2float(r0[c]), __half2float(r0[CC + c])),
                        fmaxf(__half2float(r0[(size_t)WW*CC + c]),
                              __half2float(r0[(size_t)(WW+1)*CC + c])));
        o[c] = __float2half(v);
    }
}

// ---------------- softmax: f fp16 -> attn fp16, pad zero ----------------
__global__ void softmax_kernel()
{
    const __half* p = d_f + (size_t)blockIdx.x * NKp;
    __half* q = d_attn + (size_t)blockIdx.x * NKp;
    const int tid = threadIdx.x;
    __shared__ float red[8];
    float m = -1e30f;
    for (int i = tid; i < NKr; i += 256) m = fmaxf(m, __half2float(p[i]));
    m = warpMax(m);
    if ((tid & 31) == 0) red[tid >> 5] = m;
    __syncthreads();
    if (tid < 32) { float v = (tid < 8) ? red[tid] : -1e30f; v = warpMax(v); if (tid == 0) red[0] = v; }
    __syncthreads();
    const float bm = red[0];
    __syncthreads();
    float s = 0.0f;
    for (int i = tid; i < NKr; i += 256) s += __expf(__half2float(p[i]) - bm);
    s = warpSum(s);
    if ((tid & 31) == 0) red[tid >> 5] = s;
    __syncthreads();
    if (tid < 32) { float v = (tid < 8) ? red[tid] : 0.0f; v = warpSum(v); if (tid == 0) red[0] = v; }
    __syncthreads();
    const float inv = 1.0f / red[0];
    for (int i = tid; i < NKr; i += 256)
        q[i] = __float2half(__expf(__half2float(p[i]) - bm) * inv);
    for (int i = NKr + tid; i < NKp; i += 256) q[i] = __float2half(0.0f);
}

// ---------------- BN stats over d_wy (B,C,NQ) ----------------
__global__ void bn_stats_kernel()
{
    const int c = blockIdx.x, tid = threadIdx.x;
    float s = 0.0f, ss = 0.0f;
    for (int b = 0; b < BB; b++) {
        const float* p = d_wy + ((size_t)b * CC + c) * NQ;
        for (int i = tid; i < NQ; i += 256) { float v = p[i]; s += v; ss += v * v; }
    }
    __shared__ float r1[8], r2[8];
    s = warpSum(s); ss = warpSum(ss);
    if ((tid & 31) == 0) { r1[tid >> 5] = s; r2[tid >> 5] = ss; }
    __syncthreads();
    if (tid < 32) {
        float a  = (tid < 8) ? r1[tid] : 0.0f;
        float b2 = (tid < 8) ? r2[tid] : 0.0f;
        a = warpSum(a); b2 = warpSum(b2);
        if (tid == 0) {
            const float cnt = (float)((long long)BB * NQ);
            float mean = a / cnt;
            float var = b2 / cnt - mean * mean;
            d_mean[c] = mean;
            d_istd[c] = rsqrtf(var + BN_EPS);
        }
    }
}

__global__ void bn_apply_kernel(const float* __restrict__ x,
                                const float* __restrict__ gamma,
                                const float* __restrict__ beta,
                                float* __restrict__ out)
{
    size_t i = (size_t)blockIdx.x * 256 + threadIdx.x;
    if (i >= (size_t)BB * CC * NQ) return;
    int c = (int)((i / NQ) % CC);
    out[i] = (d_wy[i] - d_mean[c]) * d_istd[c] * gamma[c] + beta[c] + x[i];
}

// ---------------- host ----------------
extern "C" void kernel_launch(void* const* d_in, const int* in_sizes, int n_in,
                              void* d_out, int out_size)
{
    (void)in_sizes; (void)n_in; (void)out_size;
    const float* x       = (const float*)d_in[0];
    const float* theta_w = (const float*)d_in[1];
    const float* theta_b = (const float*)d_in[2];
    const float* phi_w   = (const float*)d_in[3];
    const float* phi_b   = (const float*)d_in[4];
    const float* g_w     = (const float*)d_in[5];
    const float* g_b     = (const float*)d_in[6];
    const float* w_w     = (const float*)d_in[7];
    const float* w_b     = (const float*)d_in[8];
    const float* bn_g    = (const float*)d_in[9];
    const float* bn_b    = (const float*)d_in[10];
    float* out = (float*)d_out;

    cudaFuncSetAttribute(gemm_tn<float>,  cudaFuncAttributeMaxDynamicSharedMemorySize, GEMM_SMEM);
    cudaFuncSetAttribute(gemm_tn<__half>, cudaFuncAttributeMaxDynamicSharedMemorySize, GEMM_SMEM);

    void *p_xt, *p_xpt, *p_th, *p_ph, *p_g2, *p_f, *p_attn, *p_y, *p_wy;
    void *p_thw, *p_phw, *p_gw, *p_ww;
    cudaGetSymbolAddress(&p_xt, d_xt);
    cudaGetSymbolAddress(&p_xpt, d_xpt);
    cudaGetSymbolAddress(&p_th, d_th);
    cudaGetSymbolAddress(&p_ph, d_ph);
    cudaGetSymbolAddress(&p_g2, d_g2);
    cudaGetSymbolAddress(&p_f, d_f);
    cudaGetSymbolAddress(&p_attn, d_attn);
    cudaGetSymbolAddress(&p_y, d_y);
    cudaGetSymbolAddress(&p_wy, d_wy);
    cudaGetSymbolAddress(&p_thw, d_thw);
    cudaGetSymbolAddress(&p_phw, d_phw);
    cudaGetSymbolAddress(&p_gw, d_gw);
    cudaGetSymbolAddress(&p_ww, d_ww);

    const float fscale = 1.0f / sqrtf((float)CI);
    const int wsz = CI * CC;

    f2h_kernel<<<wsz/512, 256>>>(theta_w, (__half*)p_thw, wsz);
    f2h_kernel<<<wsz/512, 256>>>(phi_w,   (__half*)p_phw, wsz);
    f2h_kernel<<<wsz/512, 256>>>(g_w,     (__half*)p_gw,  wsz);
    f2h_kernel<<<wsz/512, 256>>>(w_w,     (__half*)p_ww,  wsz);
    transpose_x<<<dim3(NQ/32, CC/32, BB), dim3(32,8)>>>(x);
    pool_kernel<<<dim3(NKp, BB), 256>>>();

    // theta (B,NQ,CI) = xt @ theta_w^T + theta_b[n]   -> fp16
    gemm_tn<__half><<<dim3(CI/128, NQ/128, BB), 256, GEMM_SMEM>>>(
        (const __half*)p_xt, (const __half*)p_thw, (__half*)p_th,
        CC, CC, CC, CI, (long long)NQ*CC, 0LL, (long long)NQ*CI,
        nullptr, theta_b, 1.0f);
    // phi (B,NKp,CI) = xpt @ phi_w^T + phi_b[n]       -> fp16
    gemm_tn<__half><<<dim3(CI/128, NKp/128, BB), 256, GEMM_SMEM>>>(
        (const __half*)p_xpt, (const __half*)p_phw, (__half*)p_ph,
        CC, CC, CC, CI, (long long)NKp*CC, 0LL, (long long)NKp*CI,
        nullptr, phi_b, 1.0f);
    // g2 (B,CI,NKp) = g_w @ xpt^T + g_b[m]            -> fp16
    gemm_tn<__half><<<dim3(NKp/128, CI/128, BB), 256, GEMM_SMEM>>>(
        (const __half*)p_gw, (const __half*)p_xpt, (__half*)p_g2,
        CC, CC, CC, NKp, 0LL, (long long)NKp*CC, (long long)CI*NKp,
        g_b, nullptr, 1.0f);
    // f (B,NQ,NKp) = theta @ phi^T * scale            -> fp16
    gemm_tn<__half><<<dim3(NKp/128, NQ/128, BB), 256, GEMM_SMEM>>>(
        (const __half*)p_th, (const __half*)p_ph, (__half*)p_f,
        CI, CI, CI, NKp, (long long)NQ*CI, (long long)NKp*CI, (long long)NQ*NKp,
        nullptr, nullptr, fscale);

    softmax_kernel<<<BB*NQ, 256>>>();

    // y (B,NQ,CI) = attn @ g2^T                        -> fp16
    gemm_tn<__half><<<dim3(CI/128, NQ/128, BB), 256, GEMM_SMEM>>>(
        (const __half*)p_attn, (const __half*)p_g2, (__half*)p_y,
        NKp, NKp, NKp, CI, (long long)NQ*NKp, (long long)CI*NKp, (long long)NQ*CI,
        nullptr, nullptr, 1.0f);
    // wy (B,CC,NQ) = w_w @ y^T + w_b[m]                -> fp32
    gemm_tn<float><<<dim3(NQ/128, CC/128, BB), 256, GEMM_SMEM>>>(
        (const __half*)p_ww, (const __half*)p_y, (float*)p_wy,
        CI, CI, CI, NQ, 0LL, (long long)NQ*CI, (long long)CC*NQ,
        w_b, nullptr, 1.0f);

    bn_stats_kernel<<<CC, 256>>>();
    {
        size_t tot = (size_t)BB * CC * NQ;
        bn_apply_kernel<<<(unsigned)((tot + 255) / 256), 256>>>(x, bn_g, bn_b, out);
    }
}

// round 8
// speedup vs baseline: 8.0801x; 1.1997x over previous
#include <cuda_runtime.h>
#include <cuda_fp16.h>
#include <math.h>
#include <stdint.h>

#define BB 4
#define CC 1024
#define CI 512
#define TT 16
#define HH 28
#define WW 28
#define NQ 12544
#define NKr 3136
#define NKp 3200
#define BN_EPS 1e-5f

// ---------------- scratch ----------------
__device__ __align__(256) __half d_xt  [(size_t)BB*NQ*CC];
__device__ __align__(256) __half d_xpt [(size_t)BB*NKp*CC];
__device__ __align__(256) __half d_th  [(size_t)BB*NQ*CI];
__device__ __align__(256) __half d_ph  [(size_t)BB*NKp*CI];
__device__ __align__(256) __half d_g2  [(size_t)BB*CI*NKp];
__device__ __align__(256) __half d_f   [(size_t)BB*NQ*NKp];
__device__ __align__(256) __half d_attn[(size_t)BB*NQ*NKp];
__device__ __align__(256) __half d_y   [(size_t)BB*NQ*CI];
__device__ __align__(256) __half d_wy  [(size_t)BB*CC*NQ];
__device__ __align__(256) __half d_thw [CI*CC];
__device__ __align__(256) __half d_phw [CI*CC];
__device__ __align__(256) __half d_gw  [CI*CC];
__device__ __align__(256) __half d_ww  [CC*CI];
__device__ float d_mean[CC];
__device__ float d_istd[CC];

// ---------------- helpers ----------------
__device__ __forceinline__ uint32_t s2u(const void* p) {
    uint32_t a;
    asm("{ .reg .u64 t; cvta.to.shared.u64 t, %1; cvt.u32.u64 %0, t; }" : "=r"(a) : "l"(p));
    return a;
}
__device__ __forceinline__ float warpSum(float v) {
    #pragma unroll
    for (int o = 16; o > 0; o >>= 1) v += __shfl_xor_sync(0xffffffffu, v, o);
    return v;
}
__device__ __forceinline__ void st2(float* p, float a, float b) {
    *(float2*)p = make_float2(a, b);
}
__device__ __forceinline__ void st2(__half* p, float a, float b) {
    *(__half2*)p = __floats2half2_rn(a, b);
}

// ---------------- fp16 mma.sync TN GEMM, BK=64 ----------------
// D[M,N] = scale * A[M,K] @ B[N,K]^T (+ biasM[m]) (+ biasN[n])
#define ROW_B  144
#define TILE_B (128*ROW_B)
#define STG_B  (2*TILE_B)
#define NSTAGE 3
#define GEMM_SMEM (NSTAGE*STG_B)       // 110592 -> 2 CTAs/SM

template<typename TO>
__global__ __launch_bounds__(256, 2)
void gemm_tn(const __half* __restrict__ A, const __half* __restrict__ B,
             TO* __restrict__ D, int K, int lda, int ldb, int ldd,
             long long sA, long long sB, long long sD,
             const float* __restrict__ biasM, const float* __restrict__ biasN,
             float scale)
{
    extern __shared__ char smem[];
    const uint32_t smem_b = s2u(smem);
    const int tid = threadIdx.x, wid = tid >> 5, lane = tid & 31;
    const int wm = wid >> 2, wn = wid & 3;
    const int g = lane >> 2, tg = lane & 3;
    const int m0 = blockIdx.y << 7, n0 = blockIdx.x << 7;
    A += (long long)blockIdx.z * sA + (size_t)m0 * lda;
    B += (long long)blockIdx.z * sB + (size_t)n0 * ldb;
    D += (long long)blockIdx.z * sD;
    const int ktiles = K >> 6;

    const int prow[4] = { (tid + 0) >> 3, (tid + 256) >> 3, (tid + 512) >> 3, (tid + 768) >> 3 };
    const int pc = tid & 7;

    const uint32_t aoff = (uint32_t)(wm * 64 + (lane & 15)) * ROW_B + ((lane >> 4) << 4);
    const uint32_t boff = (uint32_t)TILE_B
                        + (uint32_t)(wn * 32 + ((lane >> 4) << 3) + (lane & 7)) * ROW_B
                        + (((lane >> 3) & 1) << 4);

    float acc[4][4][4];
    #pragma unroll
    for (int i = 0; i < 4; i++)
        #pragma unroll
        for (int j = 0; j < 4; j++)
            #pragma unroll
            for (int q = 0; q < 4; q++) acc[i][j][q] = 0.0f;

    #pragma unroll
    for (int s = 0; s < NSTAGE - 1; s++) {
        const __half* Ab = A + (s << 6) + (pc << 3);
        const __half* Bb = B + (s << 6) + (pc << 3);
        uint32_t Sa = smem_b + s * STG_B + pc * 16;
        uint32_t Sb = Sa + TILE_B;
        #pragma unroll
        for (int l = 0; l < 4; l++) {
            asm volatile("cp.async.cg.shared.global [%0], [%1], 16;"
                         :: "r"(Sa + prow[l] * ROW_B), "l"(Ab + (size_t)prow[l] * lda));
            asm volatile("cp.async.cg.shared.global [%0], [%1], 16;"
                         :: "r"(Sb + prow[l] * ROW_B), "l"(Bb + (size_t)prow[l] * ldb));
        }
        asm volatile("cp.async.commit_group;");
    }

    int sc = 0;
    for (int kt = 0; kt < ktiles; kt++) {
        const int pf = kt + NSTAGE - 1;
        if (pf < ktiles) {
            int sp = sc + NSTAGE - 1; if (sp >= NSTAGE) sp -= NSTAGE;
            const __half* Ab = A + (pf << 6) + (pc << 3);
            const __half* Bb = B + (pf << 6) + (pc << 3);
            uint32_t Sa = smem_b + sp * STG_B + pc * 16;
            uint32_t Sb = Sa + TILE_B;
            #pragma unroll
            for (int l = 0; l < 4; l++) {
                asm volatile("cp.async.cg.shared.global [%0], [%1], 16;"
                             :: "r"(Sa + prow[l] * ROW_B), "l"(Ab + (size_t)prow[l] * lda));
                asm volatile("cp.async.cg.shared.global [%0], [%1], 16;"
                             :: "r"(Sb + prow[l] * ROW_B), "l"(Bb + (size_t)prow[l] * ldb));
            }
        }
        asm volatile("cp.async.commit_group;");
        asm volatile("cp.async.wait_group %0;" :: "n"(NSTAGE - 2));
        __syncthreads();

        const uint32_t sbase = smem_b + sc * STG_B;
        const uint32_t aB = sbase + aoff;
        const uint32_t bB = sbase + boff;

        #pragma unroll
        for (int ks = 0; ks < 4; ks++) {
            const uint32_t kb = ks * 32;
            uint32_t a[4][4], b[4][2];
            #pragma unroll
            for (int mt = 0; mt < 4; mt++)
                asm volatile("ldmatrix.sync.aligned.m8n8.x4.shared.b16 {%0,%1,%2,%3}, [%4];"
                             : "=r"(a[mt][0]), "=r"(a[mt][1]), "=r"(a[mt][2]), "=r"(a[mt][3])
                             : "r"(aB + mt * (16 * ROW_B) + kb));
            asm volatile("ldmatrix.sync.aligned.m8n8.x4.shared.b16 {%0,%1,%2,%3}, [%4];"
                         : "=r"(b[0][0]), "=r"(b[0][1]), "=r"(b[1][0]), "=r"(b[1][1])
                         : "r"(bB + kb));
            asm volatile("ldmatrix.sync.aligned.m8n8.x4.shared.b16 {%0,%1,%2,%3}, [%4];"
                         : "=r"(b[2][0]), "=r"(b[2][1]), "=r"(b[3][0]), "=r"(b[3][1])
                         : "r"(bB + 16 * ROW_B + kb));
            #pragma unroll
            for (int mt = 0; mt < 4; mt++)
                #pragma unroll
                for (int nt = 0; nt < 4; nt++)
                    asm("mma.sync.aligned.m16n8k16.row.col.f32.f16.f16.f32 "
                        "{%0,%1,%2,%3}, {%4,%5,%6,%7}, {%8,%9}, {%0,%1,%2,%3};"
                        : "+f"(acc[mt][nt][0]), "+f"(acc[mt][nt][1]),
                          "+f"(acc[mt][nt][2]), "+f"(acc[mt][nt][3])
                        : "r"(a[mt][0]), "r"(a[mt][1]), "r"(a[mt][2]), "r"(a[mt][3]),
                          "r"(b[nt][0]), "r"(b[nt][1]));
        }
        __syncthreads();
        if (++sc == NSTAGE) sc = 0;
    }

    #pragma unroll
    for (int mt = 0; mt < 4; mt++) {
        const int r0 = m0 + wm * 64 + mt * 16 + g;
        const float bm0 = biasM ? biasM[r0] : 0.0f;
        const float bm1 = biasM ? biasM[r0 + 8] : 0.0f;
        #pragma unroll
        for (int nt = 0; nt < 4; nt++) {
            const int col = n0 + wn * 32 + nt * 8 + tg * 2;
            const float bn0 = biasN ? biasN[col] : 0.0f;
            const float bn1 = biasN ? biasN[col + 1] : 0.0f;
            st2(D + (size_t)r0 * ldd + col,
                acc[mt][nt][0] * scale + bm0 + bn0,
                acc[mt][nt][1] * scale + bm0 + bn1);
            st2(D + (size_t)(r0 + 8) * ldd + col,
                acc[mt][nt][2] * scale + bm1 + bn0,
                acc[mt][nt][3] * scale + bm1 + bn1);
        }
    }
}

// ---------------- fp32 -> fp16 convert (all 4 weights, one launch) ---------
__global__ void f2h4_kernel(const float* __restrict__ w0, const float* __restrict__ w1,
                            const float* __restrict__ w2, const float* __restrict__ w3)
{
    const int WSZ2 = CI * CC / 2;      // half2 count per weight
    int i = blockIdx.x * 256 + threadIdx.x;
    int seg = i / WSZ2, off = i - seg * WSZ2;
    const float* s = (seg == 0) ? w0 : (seg == 1) ? w1 : (seg == 2) ? w2 : w3;
    __half* d = (seg == 0) ? d_thw : (seg == 1) ? d_phw : (seg == 2) ? d_gw : d_ww;
    float2 v = *(const float2*)(s + 2 * off);
    *(__half2*)(d + 2 * off) = __floats2half2_rn(v.x, v.y);
}

// ---------------- transpose x (B,C,NQ) -> xt fp16 (B,NQ,C) ----------------
__global__ void transpose_x(const float* __restrict__ x)
{
    __shared__ float t[32][33];
    const int b = blockIdx.z;
    const int n0 = blockIdx.x << 5, c0 = blockIdx.y << 5;
    const int tx = threadIdx.x, ty = threadIdx.y;
    const float* xp = x + (size_t)b * CC * NQ;
    __half* xo = d_xt + (size_t)b * NQ * CC;
    #pragma unroll
    for (int i = 0; i < 4; i++)
        t[ty + i*8][tx] = xp[(size_t)(c0 + ty + i*8) * NQ + n0 + tx];
    __syncthreads();
    #pragma unroll
    for (int i = 0; i < 4; i++)
        xo[(size_t)(n0 + ty + i*8) * CC + c0 + tx] = __float2half(t[tx][ty + i*8]);
}

// ---------------- pool xt -> xpt fp16 (B,NKp,C), pad rows zero -------------
__global__ void pool_kernel()
{
    const int b = blockIdx.y, nk = blockIdx.x;
    __half2* o = (__half2*)(d_xpt + ((size_t)b * NKp + nk) * CC);
    if (nk >= NKr) {
        for (int c = threadIdx.x; c < CC/2; c += 256) o[c] = __half2half2(__float2half(0.0f));
        return;
    }
    const int wi = nk % 14, hi = (nk / 14) % 14, t = nk / 196;
    const __half2* r0 = (const __half2*)(d_xt + ((size_t)b * NQ + (size_t)(t * HH + 2 * hi) * WW + 2 * wi) * CC);
    const int s1 = CC/2, s2 = WW*CC/2, s3 = (WW+1)*CC/2;
    for (int c = threadIdx.x; c < CC/2; c += 256)
        o[c] = __hmax2(__hmax2(r0[c], r0[s1 + c]), __hmax2(r0[s2 + c], r0[s3 + c]));
}

// ---------------- softmax: f fp16 -> attn fp16 (no-shift, 1R+1W) ----------
#define SM_ITER 13      // 13*256 = 3328 >= 3136
__global__ __launch_bounds__(256)
void softmax_kernel()
{
    const __half* p = d_f + (size_t)blockIdx.x * NKp;
    __half* q = d_attn + (size_t)blockIdx.x * NKp;
    const int tid = threadIdx.x;
    __shared__ float red[8];
    float vals[SM_ITER];
    float s = 0.0f;
    #pragma unroll
    for (int j = 0; j < SM_ITER; j++) {
        int i = tid + j * 256;
        float e = 0.0f;
        if (i < NKr) e = __expf(__half2float(p[i]));
        vals[j] = e;
        s += e;
    }
    s = warpSum(s);
    if ((tid & 31) == 0) red[tid >> 5] = s;
    __syncthreads();
    if (tid < 32) { float v = (tid < 8) ? red[tid] : 0.0f; v = warpSum(v); if (tid == 0) red[0] = v; }
    __syncthreads();
    const float inv = 1.0f / red[0];
    #pragma unroll
    for (int j = 0; j < SM_ITER; j++) {
        int i = tid + j * 256;
        if (i < NKr) q[i] = __float2half(vals[j] * inv);
    }
    for (int i = NKr + tid; i < NKp; i += 256) q[i] = __float2half(0.0f);
}

// ---------------- BN stats over d_wy fp16 (B,C,NQ) ----------------
__global__ void bn_stats_kernel()
{
    const int c = blockIdx.x, tid = threadIdx.x;
    float s = 0.0f, ss = 0.0f;
    for (int b = 0; b < BB; b++) {
        const __half2* p = (const __half2*)(d_wy + ((size_t)b * CC + c) * NQ);
        for (int i = tid; i < NQ/2; i += 256) {
            float2 v = __half22float2(p[i]);
            s += v.x + v.y; ss += v.x * v.x + v.y * v.y;
        }
    }
    __shared__ float r1[8], r2[8];
    s = warpSum(s); ss = warpSum(ss);
    if ((tid & 31) == 0) { r1[tid >> 5] = s; r2[tid >> 5] = ss; }
    __syncthreads();
    if (tid < 32) {
        float a  = (tid < 8) ? r1[tid] : 0.0f;
        float b2 = (tid < 8) ? r2[tid] : 0.0f;
        a = warpSum(a); b2 = warpSum(b2);
        if (tid == 0) {
            const float cnt = (float)((long long)BB * NQ);
            float mean = a / cnt;
            float var = b2 / cnt - mean * mean;
            d_mean[c] = mean;
            d_istd[c] = rsqrtf(var + BN_EPS);
        }
    }
}

// ---------------- BN apply + residual (2 elems/thread) ----------------
__global__ void bn_apply_kernel(const float* __restrict__ x,
                                const float* __restrict__ gamma,
                                const float* __restrict__ beta,
                                float* __restrict__ out)
{
    size_t i = (size_t)blockIdx.x * 256 + threadIdx.x;   // half2 index
    if (i >= (size_t)BB * CC * NQ / 2) return;
    int c = (int)((i / (NQ/2)) % CC);
    float2 wv = __half22float2(*(const __half2*)(d_wy + 2 * i));
    float2 xv = *(const float2*)(x + 2 * i);
    const float a = d_istd[c] * gamma[c];
    const float m = d_mean[c], bt = beta[c];
    float2 r;
    r.x = (wv.x - m) * a + bt + xv.x;
    r.y = (wv.y - m) * a + bt + xv.y;
    *(float2*)(out + 2 * i) = r;
}

// ---------------- host ----------------
extern "C" void kernel_launch(void* const* d_in, const int* in_sizes, int n_in,
                              void* d_out, int out_size)
{
    (void)in_sizes; (void)n_in; (void)out_size;
    const float* x       = (const float*)d_in[0];
    const float* theta_w = (const float*)d_in[1];
    const float* theta_b = (const float*)d_in[2];
    const float* phi_w   = (const float*)d_in[3];
    const float* phi_b   = (const float*)d_in[4];
    const float* g_w     = (const float*)d_in[5];
    const float* g_b     = (const float*)d_in[6];
    const float* w_w     = (const float*)d_in[7];
    const float* w_b     = (const float*)d_in[8];
    const float* bn_g    = (const float*)d_in[9];
    const float* bn_b    = (const float*)d_in[10];
    float* out = (float*)d_out;

    cudaFuncSetAttribute(gemm_tn<float>,  cudaFuncAttributeMaxDynamicSharedMemorySize, GEMM_SMEM);
    cudaFuncSetAttribute(gemm_tn<__half>, cudaFuncAttributeMaxDynamicSharedMemorySize, GEMM_SMEM);

    void *p_xt, *p_xpt, *p_th, *p_ph, *p_g2, *p_f, *p_attn, *p_y, *p_wy;
    void *p_thw, *p_phw, *p_gw, *p_ww;
    cudaGetSymbolAddress(&p_xt, d_xt);
    cudaGetSymbolAddress(&p_xpt, d_xpt);
    cudaGetSymbolAddress(&p_th, d_th);
    cudaGetSymbolAddress(&p_ph, d_ph);
    cudaGetSymbolAddress(&p_g2, d_g2);
    cudaGetSymbolAddress(&p_f, d_f);
    cudaGetSymbolAddress(&p_attn, d_attn);
    cudaGetSymbolAddress(&p_y, d_y);
    cudaGetSymbolAddress(&p_wy, d_wy);
    cudaGetSymbolAddress(&p_thw, d_thw);
    cudaGetSymbolAddress(&p_phw, d_phw);
    cudaGetSymbolAddress(&p_gw, d_gw);
    cudaGetSymbolAddress(&p_ww, d_ww);

    const float fscale = 1.0f / sqrtf((float)CI);

    f2h4_kernel<<<4 * CI * CC / 512, 256>>>(theta_w, phi_w, g_w, w_w);
    transpose_x<<<dim3(NQ/32, CC/32, BB), dim3(32,8)>>>(x);
    pool_kernel<<<dim3(NKp, BB), 256>>>();

    // theta (B,NQ,CI) = xt @ theta_w^T + theta_b[n]
    gemm_tn<__half><<<dim3(CI/128, NQ/128, BB), 256, GEMM_SMEM>>>(
        (const __half*)p_xt, (const __half*)p_thw, (__half*)p_th,
        CC, CC, CC, CI, (long long)NQ*CC, 0LL, (long long)NQ*CI,
        nullptr, theta_b, 1.0f);
    // phi (B,NKp,CI) = xpt @ phi_w^T + phi_b[n]
    gemm_tn<__half><<<dim3(CI/128, NKp/128, BB), 256, GEMM_SMEM>>>(
        (const __half*)p_xpt, (const __half*)p_phw, (__half*)p_ph,
        CC, CC, CC, CI, (long long)NKp*CC, 0LL, (long long)NKp*CI,
        nullptr, phi_b, 1.0f);
    // g2 (B,CI,NKp) = g_w @ xpt^T + g_b[m]
    gemm_tn<__half><<<dim3(NKp/128, CI/128, BB), 256, GEMM_SMEM>>>(
        (const __half*)p_gw, (const __half*)p_xpt, (__half*)p_g2,
        CC, CC, CC, NKp, 0LL, (long long)NKp*CC, (long long)CI*NKp,
        g_b, nullptr, 1.0f);
    // f (B,NQ,NKp) = theta @ phi^T * scale -> fp16
    gemm_tn<__half><<<dim3(NKp/128, NQ/128, BB), 256, GEMM_SMEM>>>(
        (const __half*)p_th, (const __half*)p_ph, (__half*)p_f,
        CI, CI, CI, NKp, (long long)NQ*CI, (long long)NKp*CI, (long long)NQ*NKp,
        nullptr, nullptr, fscale);

    softmax_kernel<<<BB*NQ, 256>>>();

    // y (B,NQ,CI) = attn @ g2^T
    gemm_tn<__half><<<dim3(CI/128, NQ/128, BB), 256, GEMM_SMEM>>>(
        (const __half*)p_attn, (const __half*)p_g2, (__half*)p_y,
        NKp, NKp, NKp, CI, (long long)NQ*NKp, (long long)CI*NKp, (long long)NQ*CI,
        nullptr, nullptr, 1.0f);
    // wy (B,CC,NQ) = w_w @ y^T + w_b[m] -> fp16
    gemm_tn<__half><<<dim3(NQ/128, CC/128, BB), 256, GEMM_SMEM>>>(
        (const __half*)p_ww, (const __half*)p_y, (__half*)p_wy,
        CI, CI, CI, NQ, 0LL, (long long)NQ*CI, (long long)CC*NQ,
        w_b, nullptr, 1.0f);

    bn_stats_kernel<<<CC, 256>>>();
    {
        size_t tot = (size_t)BB * CC * NQ / 2;
        bn_apply_kernel<<<(unsigned)((tot + 255) / 256), 256>>>(x, bn_g, bn_b, out);
    }
}